// round 14
// baseline (speedup 1.0000x reference)
#include <cuda_runtime.h>
#include <cuda_fp16.h>
#include <math.h>
#include <cstdint>

// ---------------- problem constants ----------------
#define NNODES 8192
#define NEDGES 65536
#define DIN    768
#define DHID   768
#define H1N    8
#define H2N    1
#define NEG_SLOPE 0.2f
#define EPSV 1e-16f
#define SPLITK 3
#define K2CHUNK ((H1N * DHID) / SPLITK)     // 2048
#define MAXDEG 128

// ---------------- scratch (device globals; no allocs allowed) ----------------
__device__ __half g_h1h[(size_t)NNODES * (H1N * DHID)];    // x @ W1 fp16 [8192, 6144]
__device__ float  g_part[(size_t)SPLITK * NNODES * DHID];  // GEMM2 split-K partials
__device__ float  g_h2[(size_t)NNODES * DHID];             // o1 @ W2 summed [8192, 768]
__device__ __half g_xh [(size_t)NNODES * DIN];             // x fp16
__device__ __half g_o1h[(size_t)NNODES * (H1N * DHID)];    // elu(agg1+b1) fp16 (GEMM2 A)
__device__ __half g_w1th[(size_t)(H1N * DHID) * DIN];      // W1^T fp16 [6144, 768]
__device__ __half g_w2th[(size_t)DHID * (H1N * DHID)];     // W2^T fp16 [768, 6144]
__device__ float g_as1[NNODES * H1N];
__device__ float g_ad1[NNODES * H1N];
__device__ float g_as2[NNODES];
__device__ float g_ad2[NNODES];
__device__ int   g_deg[NNODES];
__device__ int   g_cur[NNODES];
__device__ int   g_off[NNODES + 1];
__device__ int   g_eid[NEDGES];

// ---------------- helpers ----------------
__device__ __forceinline__ void cp16(unsigned dst, const void* src) {
    asm volatile("cp.async.cg.shared.global [%0], [%1], 16;" :: "r"(dst), "l"(src));
}
__device__ __forceinline__ uint32_t smem_u32(const void* p) {
    return (uint32_t)__cvta_generic_to_shared(p);
}

#define MMA_F16(d, a, b)                                                               \
    asm volatile(                                                                      \
        "mma.sync.aligned.m16n8k16.row.col.f32.f16.f16.f32 "                           \
        "{%0,%1,%2,%3},{%4,%5,%6,%7},{%8,%9},{%0,%1,%2,%3};"                           \
        : "+f"((d)[0]), "+f"((d)[1]), "+f"((d)[2]), "+f"((d)[3])                       \
        : "r"((a)[0]), "r"((a)[1]), "r"((a)[2]), "r"((a)[3]), "r"((b)[0]), "r"((b)[1]))

#define LDSM_X4(r, addr)                                                               \
    asm volatile("ldmatrix.sync.aligned.m8n8.x4.shared.b16 {%0,%1,%2,%3}, [%4];"       \
        : "=r"((r)[0]), "=r"((r)[1]), "=r"((r)[2]), "=r"((r)[3]) : "r"(addr))

// ---------------- fp32 -> fp16 convert ----------------
__global__ void f2h_kernel(const float* __restrict__ in, __half* __restrict__ out, int n4) {
    int i = blockIdx.x * blockDim.x + threadIdx.x;
    if (i < n4) {
        float4 v = ((const float4*)in)[i];
        __half2 h0 = __floats2half2_rn(v.x, v.y);
        __half2 h1 = __floats2half2_rn(v.z, v.w);
        uint2 u;
        u.x = *(uint32_t*)&h0; u.y = *(uint32_t*)&h1;
        ((uint2*)out)[i] = u;
    }
}

// ---------------- transpose + fp16 convert: in [R,C] fp32 -> out [C,R] fp16 ----------------
__global__ void transpose_h_kernel(const float* __restrict__ in, __half* __restrict__ out,
                                   int R, int C)
{
    __shared__ float t[32][33];
    int bx = blockIdx.x * 32, by = blockIdx.y * 32;
#pragma unroll
    for (int i = 0; i < 4; i++)
        t[threadIdx.y + 8 * i][threadIdx.x] =
            in[(size_t)(by + threadIdx.y + 8 * i) * C + bx + threadIdx.x];
    __syncthreads();
#pragma unroll
    for (int i = 0; i < 4; i++)
        out[(size_t)(bx + threadIdx.y + 8 * i) * R + by + threadIdx.x] =
            __float2half_rn(t[threadIdx.x][threadIdx.y + 8 * i]);
}

// ---------------- CSR build ----------------
__global__ void zero_counts_kernel() {
    int i = blockIdx.x * blockDim.x + threadIdx.x;
    if (i < NNODES) { g_deg[i] = 0; g_cur[i] = 0; }
}
__global__ void count_kernel(const int* __restrict__ dst) {
    int e = blockIdx.x * blockDim.x + threadIdx.x;
    if (e < NEDGES) atomicAdd(&g_deg[dst[e]], 1);
}
__global__ void scan_kernel() {
    __shared__ int s[1024];
    int t = threadIdx.x;
    int base = t * 8;
    int local[8];
    int run = 0;
#pragma unroll
    for (int i = 0; i < 8; i++) { local[i] = run; run += g_deg[base + i]; }
    s[t] = run;
    __syncthreads();
    for (int o = 1; o < 1024; o <<= 1) {
        int v = (t >= o) ? s[t - o] : 0;
        __syncthreads();
        s[t] += v;
        __syncthreads();
    }
    int prev = (t == 0) ? 0 : s[t - 1];
#pragma unroll
    for (int i = 0; i < 8; i++) g_off[base + i] = prev + local[i];
    if (t == 1023) g_off[NNODES] = s[1023];
}
__global__ void scatter_kernel(const int* __restrict__ dst) {
    int e = blockIdx.x * blockDim.x + threadIdx.x;
    if (e < NEDGES) {
        int d = dst[e];
        int p = atomicAdd(&g_cur[d], 1);
        g_eid[g_off[d] + p] = e;
    }
}
// Deterministic segment ordering (freezes all downstream fp32 sum orders).
__global__ void sort_eid_kernel() {
    int d = blockIdx.x * blockDim.x + threadIdx.x;
    if (d >= NNODES) return;
    int s0 = g_off[d], s1 = g_off[d + 1];
    for (int i = s0 + 1; i < s1; i++) {
        int v = g_eid[i];
        int j = i - 1;
        while (j >= s0 && g_eid[j] > v) { g_eid[j + 1] = g_eid[j]; j--; }
        g_eid[j + 1] = v;
    }
}

// ---------------- fp16 tensor-core GEMM ----------------
// Block 128x128, 4 warps (2x2), warp tile 64x64.  K-tile 64, 3-stage cp.async, ldmatrix.
// XOR-swizzled smem rows of exactly 128B.  One barrier per K-iteration.
#define KT 64
#define HG_OPH  (128 * KT)
#define HG_STG  (2 * HG_OPH)
#define HG_SMEM (3 * HG_STG * 2)           // 98304 bytes

__device__ __forceinline__ int sw_off(int r, int c) {
    return r * KT + ((c ^ (r & 7)) << 3);
}

__global__ void __launch_bounds__(128, 2)
hgemm(const __half* __restrict__ A, const __half* __restrict__ Bt,
      float* __restrict__ Cf, __half* __restrict__ Ch,
      int lda, int kLen, int N)
{
    extern __shared__ __half hs[];

    const int tid = threadIdx.x, wid = tid >> 5, lane = tid & 31;
    const int bn = blockIdx.x, bm = blockIdx.y, bz = blockIdx.z;
    const int k0 = bz * kLen;
    const int wm = (wid & 1) * 64;
    const int wn = (wid >> 1) * 64;
    const int g = lane >> 2, tg = lane & 3;

    const __half* Ag = A + (size_t)(bm * 128) * lda + k0;
    const __half* Bg = Bt + (size_t)(bn * 128) * lda + k0;

    float acc[32][4] = {};
    const int T = kLen / KT;

    auto load_tile = [&](int t) {
        int st = t % 3;
        __half* As = hs + st * HG_STG;
        __half* Bs = As + HG_OPH;
        int kk = t * KT;
#pragma unroll
        for (int i = 0; i < 8; i++) {
            int ci = tid + i * 128;
            int r = ci >> 3, c = ci & 7;
            int off = sw_off(r, c);
            const size_t go = (size_t)r * lda + kk + c * 8;
            cp16(smem_u32(&As[off]), Ag + go);
            cp16(smem_u32(&Bs[off]), Bg + go);
        }
        asm volatile("cp.async.commit_group;");
    };

    load_tile(0);
    if (T > 1) load_tile(1);

    const int a_r = lane & 15;
    const int a_c = lane >> 4;
    const int b_r = ((lane >> 4) << 3) + (lane & 7);
    const int b_c = (lane >> 3) & 1;

    for (int t = 0; t < T; t++) {
        asm volatile("cp.async.wait_group 1;");
        __syncthreads();
        if (t + 2 < T) load_tile(t + 2);

        const __half* Ab = hs + (t % 3) * HG_STG;
        const __half* Bb = Ab + HG_OPH;
#pragma unroll
        for (int kc = 0; kc < 4; kc++) {
            uint32_t a[4][4], b[8][2];
#pragma unroll
            for (int mi = 0; mi < 4; mi++) {
                uint32_t ad = smem_u32(&Ab[sw_off(wm + mi * 16 + a_r, kc * 2 + a_c)]);
                LDSM_X4(a[mi], ad);
            }
#pragma unroll
            for (int p = 0; p < 4; p++) {
                uint32_t br[4];
                uint32_t bd = smem_u32(&Bb[sw_off(wn + p * 16 + b_r, kc * 2 + b_c)]);
                LDSM_X4(br, bd);
                b[2 * p][0] = br[0]; b[2 * p][1] = br[1];
                b[2 * p + 1][0] = br[2]; b[2 * p + 1][1] = br[3];
            }
#pragma unroll
            for (int mi = 0; mi < 4; mi++)
#pragma unroll
                for (int ni = 0; ni < 8; ni++)
                    MMA_F16(acc[mi * 8 + ni], a[mi], b[ni]);
        }
    }

    if (Ch) {
#pragma unroll
        for (int mi = 0; mi < 4; mi++) {
            int r0 = bm * 128 + wm + mi * 16 + g;
#pragma unroll
            for (int ni = 0; ni < 8; ni++) {
                int c = bn * 128 + wn + ni * 8 + tg * 2;
                __half* p = Ch + (size_t)r0 * N + c;
                __half2 v0 = __floats2half2_rn(acc[mi * 8 + ni][0], acc[mi * 8 + ni][1]);
                __half2 v1 = __floats2half2_rn(acc[mi * 8 + ni][2], acc[mi * 8 + ni][3]);
                *(__half2*)p = v0;
                *(__half2*)(p + (size_t)8 * N) = v1;
            }
        }
    } else {
        float* Cp = Cf + (size_t)bz * NNODES * DHID;
#pragma unroll
        for (int mi = 0; mi < 4; mi++) {
            int r0 = bm * 128 + wm + mi * 16 + g;
#pragma unroll
            for (int ni = 0; ni < 8; ni++) {
                int c = bn * 128 + wn + ni * 8 + tg * 2;
                float* p = Cp + (size_t)r0 * N + c;
                *(float2*)p = make_float2(acc[mi * 8 + ni][0], acc[mi * 8 + ni][1]);
                *(float2*)(p + (size_t)8 * N) = make_float2(acc[mi * 8 + ni][2], acc[mi * 8 + ni][3]);
            }
        }
    }
}

// ---------------- per-(node,head) attention coefficients (fp16 h) ----------------
__global__ void alphas_h_kernel(const __half* __restrict__ h,
                                const float* __restrict__ a_s, const float* __restrict__ a_d,
                                float* __restrict__ out_s, float* __restrict__ out_d,
                                int H, int C)
{
    int w = (blockIdx.x * blockDim.x + threadIdx.x) >> 5;
    int lane = threadIdx.x & 31;
    if (w >= NNODES * H) return;
    int n = w / H, hd = w % H;
    const __half* hp = h + (size_t)n * H * C + (size_t)hd * C;
    const float* asp = a_s + (size_t)hd * C;
    const float* adp = a_d + (size_t)hd * C;
    float ss = 0.f, sd = 0.f;
    for (int c = lane; c < C; c += 32) {
        float v = __half2float(hp[c]);
        ss += v * asp[c];
        sd += v * adp[c];
    }
#pragma unroll
    for (int o = 16; o; o >>= 1) {
        ss += __shfl_down_sync(0xffffffffu, ss, o);
        sd += __shfl_down_sync(0xffffffffu, sd, o);
    }
    if (lane == 0) { out_s[w] = ss; out_d[w] = sd; }
}

// ---------------- split-K reduce + layer-2 alphas (fused) ----------------
__global__ void reduce_alphas2_kernel(const float* __restrict__ part,
                                      float* __restrict__ h2,
                                      const float* __restrict__ a_s, const float* __restrict__ a_d,
                                      float* __restrict__ out_s, float* __restrict__ out_d)
{
    int w = (blockIdx.x * blockDim.x + threadIdx.x) >> 5;
    int lane = threadIdx.x & 31;
    if (w >= NNODES) return;
    const size_t base = (size_t)w * DHID;
    const size_t pstride = (size_t)NNODES * DHID;
    float ss = 0.f, sd = 0.f;
    for (int c = lane; c < DHID; c += 32) {
        float s = part[base + c] + part[pstride + base + c] + part[2 * pstride + base + c];
        h2[base + c] = s;
        ss += s * a_s[c];
        sd += s * a_d[c];
    }
#pragma unroll
    for (int o = 16; o; o >>= 1) {
        ss += __shfl_down_sync(0xffffffffu, ss, o);
        sd += __shfl_down_sync(0xffffffffu, sd, o);
    }
    if (lane == 0) { out_s[w] = ss; out_d[w] = sd; }
}

// ---------------- fused softmax + layer-1 aggregation ----------------
// Block = node, 256 threads. Warp hd owns head hd. Lane 0 of each warp runs the
// SAME sequential max / sum loops as the old softmax kernel (sorted segment),
// then caches a_e = w * inv in smem. Gather loop then matches the old aggregate
// exactly -> bit-identical results.
__global__ void __launch_bounds__(256)
aggregate1_fused(const int* __restrict__ src,
                 const float* __restrict__ as, const float* __restrict__ ad,
                 const __half* __restrict__ h, __half* __restrict__ out_h,
                 const float* __restrict__ bias)
{
    __shared__ float aw[H1N][MAXDEG];
    __shared__ float sm_m[H1N], sm_inv[H1N];

    int d  = blockIdx.x;
    int t  = threadIdx.x;
    int hd = t >> 5;
    int lane = t & 31;
    int s0 = g_off[d], s1 = g_off[d + 1];
    int deg = s1 - s0;
    const size_t rs = (size_t)H1N * DHID;

    float adv = ad[d * H1N + hd];
    if (lane == 0) {
        float m = -1e30f;
        for (int i = s0; i < s1; i++) {
            int e = g_eid[i];
            float x = as[src[e] * H1N + hd] + adv;
            x = (x > 0.f) ? x : NEG_SLOPE * x;
            m = fmaxf(m, x);
        }
        float sum = 0.f;
        for (int i = s0; i < s1; i++) {
            int e = g_eid[i];
            float x = as[src[e] * H1N + hd] + adv;
            x = (x > 0.f) ? x : NEG_SLOPE * x;
            sum += __expf(x - m);
        }
        float inv = 1.f / (sum + EPSV);
        sm_m[hd] = m; sm_inv[hd] = inv;
        if (deg <= MAXDEG) {
            for (int i = s0; i < s1; i++) {
                int e = g_eid[i];
                float x = as[src[e] * H1N + hd] + adv;
                x = (x > 0.f) ? x : NEG_SLOPE * x;
                aw[hd][i - s0] = __expf(x - m) * inv;
            }
        }
    }
    __syncwarp();

    size_t rowoff = (size_t)hd * DHID + (size_t)lane * 24;
    float acc[24];
#pragma unroll
    for (int j = 0; j < 24; j++) acc[j] = 0.f;

    float m = sm_m[hd], inv = sm_inv[hd];
    for (int i = s0; i < s1; i++) {
        int e = g_eid[i];
        float a;
        if (deg <= MAXDEG) {
            a = aw[hd][i - s0];
        } else {
            float x = as[src[e] * H1N + hd] + adv;
            x = (x > 0.f) ? x : NEG_SLOPE * x;
            a = __expf(x - m) * inv;
        }
        const uint4* p = (const uint4*)(h + (size_t)src[e] * rs + rowoff);
#pragma unroll
        for (int j = 0; j < 3; j++) {
            uint4 u = p[j];
            const __half2* hh = (const __half2*)&u;
#pragma unroll
            for (int k = 0; k < 4; k++) {
                float2 f = __half22float2(hh[k]);
                acc[j * 8 + k * 2]     += a * f.x;
                acc[j * 8 + k * 2 + 1] += a * f.y;
            }
        }
    }

    const float* bp = bias + rowoff;
    __half* op = out_h + (size_t)d * rs + rowoff;
#pragma unroll
    for (int j = 0; j < 3; j++) {
        uint4 u;
        __half2* hh = (__half2*)&u;
#pragma unroll
        for (int k = 0; k < 4; k++) {
            float v0 = acc[j * 8 + k * 2]     + bp[j * 8 + k * 2];
            float v1 = acc[j * 8 + k * 2 + 1] + bp[j * 8 + k * 2 + 1];
            v0 = (v0 > 0.f) ? v0 : expm1f(v0);
            v1 = (v1 > 0.f) ? v1 : expm1f(v1);
            hh[k] = __floats2half2_rn(v0, v1);
        }
        ((uint4*)op)[j] = u;
    }
}

// ---------------- fused softmax + layer-2 aggregation ----------------
// Block = node, 192 threads. Thread 0 runs the sequential softmax; all threads gather.
__global__ void __launch_bounds__(192)
aggregate2_fused(const int* __restrict__ src,
                 const float* __restrict__ as, const float* __restrict__ ad,
                 const float* __restrict__ h, float* __restrict__ out,
                 const float* __restrict__ bias)
{
    __shared__ float aw[MAXDEG];
    __shared__ float sm_m, sm_inv;

    int d = blockIdx.x;
    int t = threadIdx.x;
    int s0 = g_off[d], s1 = g_off[d + 1];
    int deg = s1 - s0;
    float adv = ad[d];

    if (t == 0) {
        float m = -1e30f;
        for (int i = s0; i < s1; i++) {
            int e = g_eid[i];
            float x = as[src[e]] + adv;
            x = (x > 0.f) ? x : NEG_SLOPE * x;
            m = fmaxf(m, x);
        }
        float sum = 0.f;
        for (int i = s0; i < s1; i++) {
            int e = g_eid[i];
            float x = as[src[e]] + adv;
            x = (x > 0.f) ? x : NEG_SLOPE * x;
            sum += __expf(x - m);
        }
        float inv = 1.f / (sum + EPSV);
        sm_m = m; sm_inv = inv;
        if (deg <= MAXDEG) {
            for (int i = s0; i < s1; i++) {
                int e = g_eid[i];
                float x = as[src[e]] + adv;
                x = (x > 0.f) ? x : NEG_SLOPE * x;
                aw[i - s0] = __expf(x - m) * inv;
            }
        }
    }
    __syncthreads();

    float m = sm_m, inv = sm_inv;
    float4 acc = make_float4(0.f, 0.f, 0.f, 0.f);
    for (int i = s0; i < s1; i++) {
        int e = g_eid[i];
        float a;
        if (deg <= MAXDEG) {
            a = aw[i - s0];
        } else {
            float x = as[src[e]] + adv;
            x = (x > 0.f) ? x : NEG_SLOPE * x;
            a = __expf(x - m) * inv;
        }
        float4 v = *(((const float4*)(h + (size_t)src[e] * DHID)) + t);
        acc.x += a * v.x; acc.y += a * v.y; acc.z += a * v.z; acc.w += a * v.w;
    }
    float4 b = *(((const float4*)bias) + t);
    acc.x += b.x; acc.y += b.y; acc.z += b.z; acc.w += b.w;
    *(((float4*)(out + (size_t)d * DHID)) + t) = acc;
}

// ---------------- launch ----------------
extern "C" void kernel_launch(void* const* d_in, const int* in_sizes, int n_in,
                              void* d_out, int out_size)
{
    const float* x    = (const float*)d_in[0];
    const float* W1   = (const float*)d_in[1];
    const float* a_s1 = (const float*)d_in[2];
    const float* a_d1 = (const float*)d_in[3];
    const float* b1   = (const float*)d_in[4];
    const float* W2   = (const float*)d_in[5];
    const float* a_s2 = (const float*)d_in[6];
    const float* a_d2 = (const float*)d_in[7];
    const float* b2   = (const float*)d_in[8];
    const int* edges  = (const int*)d_in[9];
    const int* src = edges;
    const int* dst = edges + NEDGES;
    float* out = (float*)d_out;

    float *part, *h2, *as1, *ad1, *as2, *ad2;
    __half *h1h, *xh, *o1h, *w1th, *w2th;
    cudaGetSymbolAddress((void**)&h1h,  g_h1h);
    cudaGetSymbolAddress((void**)&part, g_part);
    cudaGetSymbolAddress((void**)&h2,   g_h2);
    cudaGetSymbolAddress((void**)&xh,   g_xh);
    cudaGetSymbolAddress((void**)&o1h,  g_o1h);
    cudaGetSymbolAddress((void**)&w1th, g_w1th);
    cudaGetSymbolAddress((void**)&w2th, g_w2th);
    cudaGetSymbolAddress((void**)&as1,  g_as1);
    cudaGetSymbolAddress((void**)&ad1,  g_ad1);
    cudaGetSymbolAddress((void**)&as2,  g_as2);
    cudaGetSymbolAddress((void**)&ad2,  g_ad2);

    cudaFuncSetAttribute(hgemm, cudaFuncAttributeMaxDynamicSharedMemorySize, HG_SMEM);

    // Streams/events created once on the (uncaptured) first call.
    static cudaStream_t s2 = nullptr, s3 = nullptr;
    static cudaEvent_t evFork = nullptr, evJoin2 = nullptr, evJoin3 = nullptr;
    if (!s2) {
        cudaStreamCreateWithFlags(&s2, cudaStreamNonBlocking);
        cudaStreamCreateWithFlags(&s3, cudaStreamNonBlocking);
        cudaEventCreateWithFlags(&evFork,  cudaEventDisableTiming);
        cudaEventCreateWithFlags(&evJoin2, cudaEventDisableTiming);
        cudaEventCreateWithFlags(&evJoin3, cudaEventDisableTiming);
    }

    dim3 tblk(32, 8);

    // ---- fork ----
    cudaEventRecord(evFork, 0);
    cudaStreamWaitEvent(s2, evFork, 0);
    cudaStreamWaitEvent(s3, evFork, 0);

    // s2: CSR chain + W2 transpose
    zero_counts_kernel<<<(NNODES + 255) / 256, 256, 0, s2>>>();
    count_kernel<<<(NEDGES + 255) / 256, 256, 0, s2>>>(dst);
    scan_kernel<<<1, 1024, 0, s2>>>();
    scatter_kernel<<<(NEDGES + 255) / 256, 256, 0, s2>>>(dst);
    sort_eid_kernel<<<(NNODES + 255) / 256, 256, 0, s2>>>();
    {
        dim3 gt(DHID / 32, (H1N * DHID) / 32);
        transpose_h_kernel<<<gt, tblk, 0, s2>>>(W2, w2th, H1N * DHID, DHID);
    }
    cudaEventRecord(evJoin2, s2);

    // s3: W1 transpose
    {
        dim3 gt((H1N * DHID) / 32, DIN / 32);
        transpose_h_kernel<<<gt, tblk, 0, s3>>>(W1, w1th, DIN, H1N * DHID);
    }
    cudaEventRecord(evJoin3, s3);

    // ---- main chain ----
    f2h_kernel<<<(NNODES * DIN / 4 + 255) / 256, 256>>>(x, xh, NNODES * DIN / 4);
    cudaStreamWaitEvent(0, evJoin3, 0);
    {
        dim3 grid((H1N * DHID) / 128, NNODES / 128, 1);   // (48, 64)
        hgemm<<<grid, 128, HG_SMEM>>>(xh, w1th, nullptr, h1h, DIN, DIN, H1N * DHID);
    }
    alphas_h_kernel<<<(NNODES * H1N * 32 + 255) / 256, 256>>>(h1h, a_s1, a_d1, as1, ad1, H1N, DHID);

    cudaStreamWaitEvent(0, evJoin2, 0);

    aggregate1_fused<<<NNODES, 256>>>(src, as1, ad1, h1h, o1h, b1);
    {
        dim3 grid((H2N * DHID) / 128, NNODES / 128, SPLITK);   // (6, 64, 3)
        hgemm<<<grid, 128, HG_SMEM>>>(o1h, w2th, part, nullptr, H1N * DHID, K2CHUNK, H2N * DHID);
    }
    reduce_alphas2_kernel<<<(NNODES * 32 + 255) / 256, 256>>>(part, h2, a_s2, a_d2, as2, ad2);
    aggregate2_fused<<<NNODES, DHID / 4>>>(src, as2, ad2, h2, out, b2);
}

// round 15
// speedup vs baseline: 1.0031x; 1.0031x over previous
#include <cuda_runtime.h>
#include <cuda_fp16.h>
#include <math.h>
#include <cstdint>

// ---------------- problem constants ----------------
#define NNODES 8192
#define NEDGES 65536
#define DIN    768
#define DHID   768
#define H1N    8
#define H2N    1
#define NEG_SLOPE 0.2f
#define EPSV 1e-16f
#define SPLITK 3
#define K2CHUNK ((H1N * DHID) / SPLITK)     // 2048
#define NCHUNK 4
#define NODES_PER_CHUNK (NNODES / NCHUNK)   // 2048 = 16 M-tiles

// ---------------- scratch (device globals; no allocs allowed) ----------------
__device__ __half g_h1h[(size_t)NNODES * (H1N * DHID)];    // x @ W1 fp16 [8192, 6144]
__device__ float  g_part[(size_t)SPLITK * NNODES * DHID];  // GEMM2 split-K partials
__device__ float  g_h2[(size_t)NNODES * DHID];             // o1 @ W2 summed [8192, 768]
__device__ __half g_xh [(size_t)NNODES * DIN];             // x fp16
__device__ __half g_o1h[(size_t)NNODES * (H1N * DHID)];    // elu(agg1+b1) fp16 (GEMM2 A)
__device__ __half g_w1th[(size_t)(H1N * DHID) * DIN];      // W1^T fp16 [6144, 768]
__device__ __half g_w2th[(size_t)DHID * (H1N * DHID)];     // W2^T fp16 [768, 6144]
__device__ float g_as1[NNODES * H1N];
__device__ float g_ad1[NNODES * H1N];
__device__ float g_as2[NNODES];
__device__ float g_ad2[NNODES];
__device__ float g_alpha1[(size_t)NEDGES * H1N];
__device__ float g_alpha2[(size_t)NEDGES];
__device__ int   g_deg[NNODES];
__device__ int   g_cur[NNODES];
__device__ int   g_off[NNODES + 1];
__device__ int   g_eid[NEDGES];

// ---------------- helpers ----------------
__device__ __forceinline__ void cp16(unsigned dst, const void* src) {
    asm volatile("cp.async.cg.shared.global [%0], [%1], 16;" :: "r"(dst), "l"(src));
}
__device__ __forceinline__ uint32_t smem_u32(const void* p) {
    return (uint32_t)__cvta_generic_to_shared(p);
}

#define MMA_F16(d, a, b)                                                               \
    asm volatile(                                                                      \
        "mma.sync.aligned.m16n8k16.row.col.f32.f16.f16.f32 "                           \
        "{%0,%1,%2,%3},{%4,%5,%6,%7},{%8,%9},{%0,%1,%2,%3};"                           \
        : "+f"((d)[0]), "+f"((d)[1]), "+f"((d)[2]), "+f"((d)[3])                       \
        : "r"((a)[0]), "r"((a)[1]), "r"((a)[2]), "r"((a)[3]), "r"((b)[0]), "r"((b)[1]))

#define LDSM_X4(r, addr)                                                               \
    asm volatile("ldmatrix.sync.aligned.m8n8.x4.shared.b16 {%0,%1,%2,%3}, [%4];"       \
        : "=r"((r)[0]), "=r"((r)[1]), "=r"((r)[2]), "=r"((r)[3]) : "r"(addr))

// ---------------- fp32 -> fp16 convert ----------------
__global__ void f2h_kernel(const float* __restrict__ in, __half* __restrict__ out, int n4) {
    int i = blockIdx.x * blockDim.x + threadIdx.x;
    if (i < n4) {
        float4 v = ((const float4*)in)[i];
        __half2 h0 = __floats2half2_rn(v.x, v.y);
        __half2 h1 = __floats2half2_rn(v.z, v.w);
        uint2 u;
        u.x = *(uint32_t*)&h0; u.y = *(uint32_t*)&h1;
        ((uint2*)out)[i] = u;
    }
}

// ---------------- transpose + fp16 convert: in [R,C] fp32 -> out [C,R] fp16 ----------------
__global__ void transpose_h_kernel(const float* __restrict__ in, __half* __restrict__ out,
                                   int R, int C)
{
    __shared__ float t[32][33];
    int bx = blockIdx.x * 32, by = blockIdx.y * 32;
#pragma unroll
    for (int i = 0; i < 4; i++)
        t[threadIdx.y + 8 * i][threadIdx.x] =
            in[(size_t)(by + threadIdx.y + 8 * i) * C + bx + threadIdx.x];
    __syncthreads();
#pragma unroll
    for (int i = 0; i < 4; i++)
        out[(size_t)(bx + threadIdx.y + 8 * i) * R + by + threadIdx.x] =
            __float2half_rn(t[threadIdx.x][threadIdx.y + 8 * i]);
}

// ---------------- CSR build ----------------
__global__ void zero_counts_kernel() {
    int i = blockIdx.x * blockDim.x + threadIdx.x;
    if (i < NNODES) { g_deg[i] = 0; g_cur[i] = 0; }
}
__global__ void count_kernel(const int* __restrict__ dst) {
    int e = blockIdx.x * blockDim.x + threadIdx.x;
    if (e < NEDGES) atomicAdd(&g_deg[dst[e]], 1);
}
__global__ void scan_kernel() {
    __shared__ int s[1024];
    int t = threadIdx.x;
    int base = t * 8;
    int local[8];
    int run = 0;
#pragma unroll
    for (int i = 0; i < 8; i++) { local[i] = run; run += g_deg[base + i]; }
    s[t] = run;
    __syncthreads();
    for (int o = 1; o < 1024; o <<= 1) {
        int v = (t >= o) ? s[t - o] : 0;
        __syncthreads();
        s[t] += v;
        __syncthreads();
    }
    int prev = (t == 0) ? 0 : s[t - 1];
#pragma unroll
    for (int i = 0; i < 8; i++) g_off[base + i] = prev + local[i];
    if (t == 1023) g_off[NNODES] = s[1023];
}
__global__ void scatter_kernel(const int* __restrict__ dst) {
    int e = blockIdx.x * blockDim.x + threadIdx.x;
    if (e < NEDGES) {
        int d = dst[e];
        int p = atomicAdd(&g_cur[d], 1);
        g_eid[g_off[d] + p] = e;
    }
}
// Deterministic segment ordering (freezes all downstream fp32 sum orders).
__global__ void sort_eid_kernel() {
    int d = blockIdx.x * blockDim.x + threadIdx.x;
    if (d >= NNODES) return;
    int s0 = g_off[d], s1 = g_off[d + 1];
    for (int i = s0 + 1; i < s1; i++) {
        int v = g_eid[i];
        int j = i - 1;
        while (j >= s0 && g_eid[j] > v) { g_eid[j + 1] = g_eid[j]; j--; }
        g_eid[j + 1] = v;
    }
}

// ---------------- fp16 tensor-core GEMM ----------------
// Block 128x128, 4 warps (2x2), warp tile 64x64.  K-tile 64, 3-stage cp.async, ldmatrix.
// XOR-swizzled smem rows of exactly 128B.  One barrier per K-iteration.
#define KT 64
#define HG_OPH  (128 * KT)
#define HG_STG  (2 * HG_OPH)
#define HG_SMEM (3 * HG_STG * 2)           // 98304 bytes

__device__ __forceinline__ int sw_off(int r, int c) {
    return r * KT + ((c ^ (r & 7)) << 3);
}

__global__ void __launch_bounds__(128, 2)
hgemm(const __half* __restrict__ A, const __half* __restrict__ Bt,
      float* __restrict__ Cf, __half* __restrict__ Ch,
      int lda, int kLen, int N)
{
    extern __shared__ __half hs[];

    const int tid = threadIdx.x, wid = tid >> 5, lane = tid & 31;
    const int bn = blockIdx.x, bm = blockIdx.y, bz = blockIdx.z;
    const int k0 = bz * kLen;
    const int wm = (wid & 1) * 64;
    const int wn = (wid >> 1) * 64;
    const int g = lane >> 2, tg = lane & 3;

    const __half* Ag = A + (size_t)(bm * 128) * lda + k0;
    const __half* Bg = Bt + (size_t)(bn * 128) * lda + k0;

    float acc[32][4] = {};
    const int T = kLen / KT;

    auto load_tile = [&](int t) {
        int st = t % 3;
        __half* As = hs + st * HG_STG;
        __half* Bs = As + HG_OPH;
        int kk = t * KT;
#pragma unroll
        for (int i = 0; i < 8; i++) {
            int ci = tid + i * 128;
            int r = ci >> 3, c = ci & 7;
            int off = sw_off(r, c);
            const size_t go = (size_t)r * lda + kk + c * 8;
            cp16(smem_u32(&As[off]), Ag + go);
            cp16(smem_u32(&Bs[off]), Bg + go);
        }
        asm volatile("cp.async.commit_group;");
    };

    load_tile(0);
    if (T > 1) load_tile(1);

    const int a_r = lane & 15;
    const int a_c = lane >> 4;
    const int b_r = ((lane >> 4) << 3) + (lane & 7);
    const int b_c = (lane >> 3) & 1;

    for (int t = 0; t < T; t++) {
        asm volatile("cp.async.wait_group 1;");
        __syncthreads();
        if (t + 2 < T) load_tile(t + 2);

        const __half* Ab = hs + (t % 3) * HG_STG;
        const __half* Bb = Ab + HG_OPH;
#pragma unroll
        for (int kc = 0; kc < 4; kc++) {
            uint32_t a[4][4], b[8][2];
#pragma unroll
            for (int mi = 0; mi < 4; mi++) {
                uint32_t ad = smem_u32(&Ab[sw_off(wm + mi * 16 + a_r, kc * 2 + a_c)]);
                LDSM_X4(a[mi], ad);
            }
#pragma unroll
            for (int p = 0; p < 4; p++) {
                uint32_t br[4];
                uint32_t bd = smem_u32(&Bb[sw_off(wn + p * 16 + b_r, kc * 2 + b_c)]);
                LDSM_X4(br, bd);
                b[2 * p][0] = br[0]; b[2 * p][1] = br[1];
                b[2 * p + 1][0] = br[2]; b[2 * p + 1][1] = br[3];
            }
#pragma unroll
            for (int mi = 0; mi < 4; mi++)
#pragma unroll
                for (int ni = 0; ni < 8; ni++)
                    MMA_F16(acc[mi * 8 + ni], a[mi], b[ni]);
        }
    }

    if (Ch) {
#pragma unroll
        for (int mi = 0; mi < 4; mi++) {
            int r0 = bm * 128 + wm + mi * 16 + g;
#pragma unroll
            for (int ni = 0; ni < 8; ni++) {
                int c = bn * 128 + wn + ni * 8 + tg * 2;
                __half* p = Ch + (size_t)r0 * N + c;
                __half2 v0 = __floats2half2_rn(acc[mi * 8 + ni][0], acc[mi * 8 + ni][1]);
                __half2 v1 = __floats2half2_rn(acc[mi * 8 + ni][2], acc[mi * 8 + ni][3]);
                *(__half2*)p = v0;
                *(__half2*)(p + (size_t)8 * N) = v1;
            }
        }
    } else {
        float* Cp = Cf + (size_t)bz * NNODES * DHID;
#pragma unroll
        for (int mi = 0; mi < 4; mi++) {
            int r0 = bm * 128 + wm + mi * 16 + g;
#pragma unroll
            for (int ni = 0; ni < 8; ni++) {
                int c = bn * 128 + wn + ni * 8 + tg * 2;
                float* p = Cp + (size_t)r0 * N + c;
                *(float2*)p = make_float2(acc[mi * 8 + ni][0], acc[mi * 8 + ni][1]);
                *(float2*)(p + (size_t)8 * N) = make_float2(acc[mi * 8 + ni][2], acc[mi * 8 + ni][3]);
            }
        }
    }
}

// ---------------- per-(node,head) attention coefficients (fp16 h) ----------------
__global__ void alphas_h_kernel(const __half* __restrict__ h,
                                const float* __restrict__ a_s, const float* __restrict__ a_d,
                                float* __restrict__ out_s, float* __restrict__ out_d,
                                int H, int C)
{
    int w = (blockIdx.x * blockDim.x + threadIdx.x) >> 5;
    int lane = threadIdx.x & 31;
    if (w >= NNODES * H) return;
    int n = w / H, hd = w % H;
    const __half* hp = h + (size_t)n * H * C + (size_t)hd * C;
    const float* asp = a_s + (size_t)hd * C;
    const float* adp = a_d + (size_t)hd * C;
    float ss = 0.f, sd = 0.f;
    for (int c = lane; c < C; c += 32) {
        float v = __half2float(hp[c]);
        ss += v * asp[c];
        sd += v * adp[c];
    }
#pragma unroll
    for (int o = 16; o; o >>= 1) {
        ss += __shfl_down_sync(0xffffffffu, ss, o);
        sd += __shfl_down_sync(0xffffffffu, sd, o);
    }
    if (lane == 0) { out_s[w] = ss; out_d[w] = sd; }
}

// ---------------- split-K reduce + layer-2 alphas (fused) ----------------
__global__ void reduce_alphas2_kernel(const float* __restrict__ part,
                                      float* __restrict__ h2,
                                      const float* __restrict__ a_s, const float* __restrict__ a_d,
                                      float* __restrict__ out_s, float* __restrict__ out_d)
{
    int w = (blockIdx.x * blockDim.x + threadIdx.x) >> 5;
    int lane = threadIdx.x & 31;
    if (w >= NNODES) return;
    const size_t base = (size_t)w * DHID;
    const size_t pstride = (size_t)NNODES * DHID;
    float ss = 0.f, sd = 0.f;
    for (int c = lane; c < DHID; c += 32) {
        float s = part[base + c] + part[pstride + base + c] + part[2 * pstride + base + c];
        h2[base + c] = s;
        ss += s * a_s[c];
        sd += s * a_d[c];
    }
#pragma unroll
    for (int o = 16; o; o >>= 1) {
        ss += __shfl_down_sync(0xffffffffu, ss, o);
        sd += __shfl_down_sync(0xffffffffu, sd, o);
    }
    if (lane == 0) { out_s[w] = ss; out_d[w] = sd; }
}

// ---------------- per-(dst,head) segment softmax ----------------
__global__ void softmax_kernel(const int* __restrict__ src,
                               const float* __restrict__ as, const float* __restrict__ ad,
                               float* __restrict__ alpha, int H)
{
    int idx = blockIdx.x * blockDim.x + threadIdx.x;
    if (idx >= NNODES * H) return;
    int d = idx / H, hd = idx % H;
    int s0 = g_off[d], s1 = g_off[d + 1];
    if (s0 == s1) return;
    float adv = ad[idx];

    float m = -1e30f;
    for (int i = s0; i < s1; i++) {
        int e = g_eid[i];
        float x = as[src[e] * H + hd] + adv;
        x = (x > 0.f) ? x : NEG_SLOPE * x;
        m = fmaxf(m, x);
    }
    float sum = 0.f;
    for (int i = s0; i < s1; i++) {
        int e = g_eid[i];
        float x = as[src[e] * H + hd] + adv;
        x = (x > 0.f) ? x : NEG_SLOPE * x;
        float w = __expf(x - m);
        alpha[(size_t)e * H + hd] = w;
        sum += w;
    }
    float inv = 1.f / (sum + EPSV);
    for (int i = s0; i < s1; i++) {
        int e = g_eid[i];
        alpha[(size_t)e * H + hd] *= inv;
    }
}

// ---------------- layer-1 aggregation: one block per node (chunked by nodeBase) ----------------
__global__ void __launch_bounds__(256)
aggregate1_kernel(const int* __restrict__ src, const float* __restrict__ alpha,
                  const __half* __restrict__ h, __half* __restrict__ out_h,
                  const float* __restrict__ bias, int nodeBase)
{
    int d  = blockIdx.x + nodeBase;
    int t  = threadIdx.x;
    int hd = t >> 5;
    size_t rowoff = (size_t)hd * DHID + (size_t)(t & 31) * 24;
    int s0 = g_off[d], s1 = g_off[d + 1];
    const size_t rs = (size_t)H1N * DHID;

    float acc[24];
#pragma unroll
    for (int j = 0; j < 24; j++) acc[j] = 0.f;

    for (int i = s0; i < s1; i++) {
        int e = g_eid[i];
        float a = alpha[(size_t)e * H1N + hd];
        const uint4* p = (const uint4*)(h + (size_t)src[e] * rs + rowoff);
#pragma unroll
        for (int j = 0; j < 3; j++) {
            uint4 u = p[j];
            const __half2* hh = (const __half2*)&u;
#pragma unroll
            for (int k = 0; k < 4; k++) {
                float2 f = __half22float2(hh[k]);
                acc[j * 8 + k * 2]     += a * f.x;
                acc[j * 8 + k * 2 + 1] += a * f.y;
            }
        }
    }

    const float* bp = bias + rowoff;
    __half* op = out_h + (size_t)d * rs + rowoff;
#pragma unroll
    for (int j = 0; j < 3; j++) {
        uint4 u;
        __half2* hh = (__half2*)&u;
#pragma unroll
        for (int k = 0; k < 4; k++) {
            float v0 = acc[j * 8 + k * 2]     + bp[j * 8 + k * 2];
            float v1 = acc[j * 8 + k * 2 + 1] + bp[j * 8 + k * 2 + 1];
            v0 = (v0 > 0.f) ? v0 : expm1f(v0);
            v1 = (v1 > 0.f) ? v1 : expm1f(v1);
            hh[k] = __floats2half2_rn(v0, v1);
        }
        ((uint4*)op)[j] = u;
    }
}

// ---------------- layer-2 aggregation: fp32 gather, fp32 out ----------------
__global__ void __launch_bounds__(192)
aggregate2_kernel(const int* __restrict__ src, const float* __restrict__ alpha,
                  const float* __restrict__ h, float* __restrict__ out,
                  const float* __restrict__ bias)
{
    int d = blockIdx.x;
    int t = threadIdx.x;
    int s0 = g_off[d], s1 = g_off[d + 1];

    float4 acc = make_float4(0.f, 0.f, 0.f, 0.f);
    for (int i = s0; i < s1; i++) {
        int e = g_eid[i];
        float a = alpha[e];
        float4 v = *(((const float4*)(h + (size_t)src[e] * DHID)) + t);
        acc.x += a * v.x; acc.y += a * v.y; acc.z += a * v.z; acc.w += a * v.w;
    }
    float4 b = *(((const float4*)bias) + t);
    acc.x += b.x; acc.y += b.y; acc.z += b.z; acc.w += b.w;
    *(((float4*)(out + (size_t)d * DHID)) + t) = acc;
}

// ---------------- launch ----------------
extern "C" void kernel_launch(void* const* d_in, const int* in_sizes, int n_in,
                              void* d_out, int out_size)
{
    const float* x    = (const float*)d_in[0];
    const float* W1   = (const float*)d_in[1];
    const float* a_s1 = (const float*)d_in[2];
    const float* a_d1 = (const float*)d_in[3];
    const float* b1   = (const float*)d_in[4];
    const float* W2   = (const float*)d_in[5];
    const float* a_s2 = (const float*)d_in[6];
    const float* a_d2 = (const float*)d_in[7];
    const float* b2   = (const float*)d_in[8];
    const int* edges  = (const int*)d_in[9];
    const int* src = edges;
    const int* dst = edges + NEDGES;
    float* out = (float*)d_out;

    float *part, *h2, *as1, *ad1, *as2, *ad2, *al1, *al2;
    __half *h1h, *xh, *o1h, *w1th, *w2th;
    cudaGetSymbolAddress((void**)&h1h,  g_h1h);
    cudaGetSymbolAddress((void**)&part, g_part);
    cudaGetSymbolAddress((void**)&h2,   g_h2);
    cudaGetSymbolAddress((void**)&xh,   g_xh);
    cudaGetSymbolAddress((void**)&o1h,  g_o1h);
    cudaGetSymbolAddress((void**)&w1th, g_w1th);
    cudaGetSymbolAddress((void**)&w2th, g_w2th);
    cudaGetSymbolAddress((void**)&as1,  g_as1);
    cudaGetSymbolAddress((void**)&ad1,  g_ad1);
    cudaGetSymbolAddress((void**)&as2,  g_as2);
    cudaGetSymbolAddress((void**)&ad2,  g_ad2);
    cudaGetSymbolAddress((void**)&al1,  g_alpha1);
    cudaGetSymbolAddress((void**)&al2,  g_alpha2);

    cudaFuncSetAttribute(hgemm, cudaFuncAttributeMaxDynamicSharedMemorySize, HG_SMEM);

    // Streams/events created once on the (uncaptured) first call.
    static cudaStream_t s2 = nullptr, s3 = nullptr;
    static cudaEvent_t evFork = nullptr, evJoin2 = nullptr, evJoin3 = nullptr, evG2 = nullptr;
    static cudaEvent_t evC[NCHUNK] = {};
    if (!s2) {
        cudaStreamCreateWithFlags(&s2, cudaStreamNonBlocking);
        cudaStreamCreateWithFlags(&s3, cudaStreamNonBlocking);
        cudaEventCreateWithFlags(&evFork,  cudaEventDisableTiming);
        cudaEventCreateWithFlags(&evJoin2, cudaEventDisableTiming);
        cudaEventCreateWithFlags(&evJoin3, cudaEventDisableTiming);
        cudaEventCreateWithFlags(&evG2,    cudaEventDisableTiming);
        for (int c = 0; c < NCHUNK; c++)
            cudaEventCreateWithFlags(&evC[c], cudaEventDisableTiming);
    }

    dim3 tblk(32, 8);

    // ---- fork ----
    cudaEventRecord(evFork, 0);
    cudaStreamWaitEvent(s2, evFork, 0);
    cudaStreamWaitEvent(s3, evFork, 0);

    // s2: CSR chain + W2 transpose (GEMM2 also runs on s2 later -> in-order dep on W2t)
    zero_counts_kernel<<<(NNODES + 255) / 256, 256, 0, s2>>>();
    count_kernel<<<(NEDGES + 255) / 256, 256, 0, s2>>>(dst);
    scan_kernel<<<1, 1024, 0, s2>>>();
    scatter_kernel<<<(NEDGES + 255) / 256, 256, 0, s2>>>(dst);
    sort_eid_kernel<<<(NNODES + 255) / 256, 256, 0, s2>>>();
    {
        dim3 gt(DHID / 32, (H1N * DHID) / 32);
        transpose_h_kernel<<<gt, tblk, 0, s2>>>(W2, w2th, H1N * DHID, DHID);
    }
    cudaEventRecord(evJoin2, s2);

    // s3: W1 transpose
    {
        dim3 gt((H1N * DHID) / 32, DIN / 32);
        transpose_h_kernel<<<gt, tblk, 0, s3>>>(W1, w1th, DIN, H1N * DHID);
    }
    cudaEventRecord(evJoin3, s3);

    // ---- main chain ----
    f2h_kernel<<<(NNODES * DIN / 4 + 255) / 256, 256>>>(x, xh, NNODES * DIN / 4);
    cudaStreamWaitEvent(0, evJoin3, 0);
    {
        dim3 grid((H1N * DHID) / 128, NNODES / 128, 1);   // (48, 64)
        hgemm<<<grid, 128, HG_SMEM>>>(xh, w1th, nullptr, h1h, DIN, DIN, H1N * DHID);
    }
    alphas_h_kernel<<<(NNODES * H1N * 32 + 255) / 256, 256>>>(h1h, a_s1, a_d1, as1, ad1, H1N, DHID);

    cudaStreamWaitEvent(0, evJoin2, 0);   // CSR ready

    softmax_kernel<<<(NNODES * H1N + 255) / 256, 256>>>(src, as1, ad1, al1, H1N);

    // ---- chunked aggregate1 (main) overlapped with chunked GEMM2 (s2) ----
    for (int c = 0; c < NCHUNK; c++) {
        aggregate1_kernel<<<NODES_PER_CHUNK, 256>>>(src, al1, h1h, o1h, b1,
                                                    c * NODES_PER_CHUNK);
        cudaEventRecord(evC[c], 0);
        cudaStreamWaitEvent(s2, evC[c], 0);
        dim3 grid((H2N * DHID) / 128, NODES_PER_CHUNK / 128, SPLITK);   // (6, 16, 3)
        const __half* Ac = o1h + (size_t)c * NODES_PER_CHUNK * (H1N * DHID);
        float* Cc = part + (size_t)c * NODES_PER_CHUNK * DHID;
        hgemm<<<grid, 128, HG_SMEM, s2>>>(Ac, w2th, Cc, nullptr,
                                          H1N * DHID, K2CHUNK, H2N * DHID);
    }
    cudaEventRecord(evG2, s2);
    cudaStreamWaitEvent(0, evG2, 0);

    reduce_alphas2_kernel<<<(NNODES * 32 + 255) / 256, 256>>>(part, h2, a_s2, a_d2, as2, ad2);
    softmax_kernel<<<(NNODES + 255) / 256, 256>>>(src, as2, ad2, al2, H2N);
    aggregate2_kernel<<<NNODES, DHID / 4>>>(src, al2, h2, out, b2);
}

// round 16
// speedup vs baseline: 1.0720x; 1.0687x over previous
#include <cuda_runtime.h>
#include <cuda_fp16.h>
#include <math.h>
#include <cstdint>

// ---------------- problem constants ----------------
#define NNODES 8192
#define NEDGES 65536
#define DIN    768
#define DHID   768
#define H1N    8
#define H2N    1
#define NEG_SLOPE 0.2f
#define EPSV 1e-16f
#define SPLITK 3
#define K2CHUNK ((H1N * DHID) / SPLITK)     // 2048
#define NSLICE 96                            // 48 bn-tiles x 2 wn-halves

// ---------------- scratch (device globals; no allocs allowed) ----------------
__device__ __half g_h1h[(size_t)NNODES * (H1N * DHID)];    // x @ W1 fp16 [8192, 6144]
__device__ float  g_part[(size_t)SPLITK * NNODES * DHID];  // GEMM2 split-K partials
__device__ float  g_h2[(size_t)NNODES * DHID];             // o1 @ W2 summed [8192, 768]
__device__ __half g_xh [(size_t)NNODES * DIN];             // x fp16
__device__ __half g_o1h[(size_t)NNODES * (H1N * DHID)];    // elu(agg1+b1) fp16 (GEMM2 A)
__device__ __half g_w1th[(size_t)(H1N * DHID) * DIN];      // W1^T fp16 [6144, 768]
__device__ __half g_w2th[(size_t)DHID * (H1N * DHID)];     // W2^T fp16 [768, 6144]
__device__ float g_asp[(size_t)NNODES * NSLICE];           // alphas1 slice partials (a_src)
__device__ float g_adp[(size_t)NNODES * NSLICE];           // alphas1 slice partials (a_dst)
__device__ float g_as1[NNODES * H1N];
__device__ float g_ad1[NNODES * H1N];
__device__ float g_as2[NNODES];
__device__ float g_ad2[NNODES];
__device__ float g_alpha1[(size_t)NEDGES * H1N];
__device__ float g_alpha2[(size_t)NEDGES];
__device__ int   g_deg[NNODES];
__device__ int   g_cur[NNODES];
__device__ int   g_off[NNODES + 1];
__device__ int   g_eid[NEDGES];

// ---------------- helpers ----------------
__device__ __forceinline__ void cp16(unsigned dst, const void* src) {
    asm volatile("cp.async.cg.shared.global [%0], [%1], 16;" :: "r"(dst), "l"(src));
}
__device__ __forceinline__ uint32_t smem_u32(const void* p) {
    return (uint32_t)__cvta_generic_to_shared(p);
}

#define MMA_F16(d, a, b)                                                               \
    asm volatile(                                                                      \
        "mma.sync.aligned.m16n8k16.row.col.f32.f16.f16.f32 "                           \
        "{%0,%1,%2,%3},{%4,%5,%6,%7},{%8,%9},{%0,%1,%2,%3};"                           \
        : "+f"((d)[0]), "+f"((d)[1]), "+f"((d)[2]), "+f"((d)[3])                       \
        : "r"((a)[0]), "r"((a)[1]), "r"((a)[2]), "r"((a)[3]), "r"((b)[0]), "r"((b)[1]))

#define LDSM_X4(r, addr)                                                               \
    asm volatile("ldmatrix.sync.aligned.m8n8.x4.shared.b16 {%0,%1,%2,%3}, [%4];"       \
        : "=r"((r)[0]), "=r"((r)[1]), "=r"((r)[2]), "=r"((r)[3]) : "r"(addr))

// ---------------- fp32 -> fp16 convert ----------------
__global__ void f2h_kernel(const float* __restrict__ in, __half* __restrict__ out, int n4) {
    int i = blockIdx.x * blockDim.x + threadIdx.x;
    if (i < n4) {
        float4 v = ((const float4*)in)[i];
        __half2 h0 = __floats2half2_rn(v.x, v.y);
        __half2 h1 = __floats2half2_rn(v.z, v.w);
        uint2 u;
        u.x = *(uint32_t*)&h0; u.y = *(uint32_t*)&h1;
        ((uint2*)out)[i] = u;
    }
}

// ---------------- transpose + fp16 convert: in [R,C] fp32 -> out [C,R] fp16 ----------------
__global__ void transpose_h_kernel(const float* __restrict__ in, __half* __restrict__ out,
                                   int R, int C)
{
    __shared__ float t[32][33];
    int bx = blockIdx.x * 32, by = blockIdx.y * 32;
#pragma unroll
    for (int i = 0; i < 4; i++)
        t[threadIdx.y + 8 * i][threadIdx.x] =
            in[(size_t)(by + threadIdx.y + 8 * i) * C + bx + threadIdx.x];
    __syncthreads();
#pragma unroll
    for (int i = 0; i < 4; i++)
        out[(size_t)(bx + threadIdx.y + 8 * i) * R + by + threadIdx.x] =
            __float2half_rn(t[threadIdx.x][threadIdx.y + 8 * i]);
}

// ---------------- CSR build ----------------
__global__ void zero_counts_kernel() {
    int i = blockIdx.x * blockDim.x + threadIdx.x;
    if (i < NNODES) { g_deg[i] = 0; g_cur[i] = 0; }
}
__global__ void count_kernel(const int* __restrict__ dst) {
    int e = blockIdx.x * blockDim.x + threadIdx.x;
    if (e < NEDGES) atomicAdd(&g_deg[dst[e]], 1);
}
__global__ void scan_kernel() {
    __shared__ int s[1024];
    int t = threadIdx.x;
    int base = t * 8;
    int local[8];
    int run = 0;
#pragma unroll
    for (int i = 0; i < 8; i++) { local[i] = run; run += g_deg[base + i]; }
    s[t] = run;
    __syncthreads();
    for (int o = 1; o < 1024; o <<= 1) {
        int v = (t >= o) ? s[t - o] : 0;
        __syncthreads();
        s[t] += v;
        __syncthreads();
    }
    int prev = (t == 0) ? 0 : s[t - 1];
#pragma unroll
    for (int i = 0; i < 8; i++) g_off[base + i] = prev + local[i];
    if (t == 1023) g_off[NNODES] = s[1023];
}
__global__ void scatter_kernel(const int* __restrict__ dst) {
    int e = blockIdx.x * blockDim.x + threadIdx.x;
    if (e < NEDGES) {
        int d = dst[e];
        int p = atomicAdd(&g_cur[d], 1);
        g_eid[g_off[d] + p] = e;
    }
}
// Deterministic segment ordering (freezes all downstream fp32 sum orders).
__global__ void sort_eid_kernel() {
    int d = blockIdx.x * blockDim.x + threadIdx.x;
    if (d >= NNODES) return;
    int s0 = g_off[d], s1 = g_off[d + 1];
    for (int i = s0 + 1; i < s1; i++) {
        int v = g_eid[i];
        int j = i - 1;
        while (j >= s0 && g_eid[j] > v) { g_eid[j + 1] = g_eid[j]; j--; }
        g_eid[j + 1] = v;
    }
}

// ---------------- fp16 tensor-core GEMM (+ optional fused alphas partials) ----------------
// Block 128x128, 4 warps (2x2), warp tile 64x64.  K-tile 64, 3-stage cp.async, ldmatrix.
// XOR-swizzled smem rows of exactly 128B.  One barrier per K-iteration.
// When asp != nullptr (GEMM1): also computes per-row partial dots of C with a_s / a_d
// over this CTA's 64-col warp slice, written to asp/adp[row * NSLICE + bn*2 + wn/64].
#define KT 64
#define HG_OPH  (128 * KT)
#define HG_STG  (2 * HG_OPH)
#define HG_SMEM (3 * HG_STG * 2)           // 98304 bytes

__device__ __forceinline__ int sw_off(int r, int c) {
    return r * KT + ((c ^ (r & 7)) << 3);
}

__global__ void __launch_bounds__(128, 2)
hgemm(const __half* __restrict__ A, const __half* __restrict__ Bt,
      float* __restrict__ Cf, __half* __restrict__ Ch,
      const float* __restrict__ a_s, const float* __restrict__ a_d,
      float* __restrict__ asp, float* __restrict__ adp,
      int lda, int kLen, int N)
{
    extern __shared__ __half hs[];
    __shared__ float s_as[128], s_ad[128];

    const int tid = threadIdx.x, wid = tid >> 5, lane = tid & 31;
    const int bn = blockIdx.x, bm = blockIdx.y, bz = blockIdx.z;
    const int k0 = bz * kLen;
    const int wm = (wid & 1) * 64;
    const int wn = (wid >> 1) * 64;
    const int g = lane >> 2, tg = lane & 3;

    if (asp && tid < 128) {
        s_as[tid] = a_s[bn * 128 + tid];
        s_ad[tid] = a_d[bn * 128 + tid];
    }

    const __half* Ag = A + (size_t)(bm * 128) * lda + k0;
    const __half* Bg = Bt + (size_t)(bn * 128) * lda + k0;

    float acc[32][4] = {};
    const int T = kLen / KT;

    auto load_tile = [&](int t) {
        int st = t % 3;
        __half* As = hs + st * HG_STG;
        __half* Bs = As + HG_OPH;
        int kk = t * KT;
#pragma unroll
        for (int i = 0; i < 8; i++) {
            int ci = tid + i * 128;
            int r = ci >> 3, c = ci & 7;
            int off = sw_off(r, c);
            const size_t go = (size_t)r * lda + kk + c * 8;
            cp16(smem_u32(&As[off]), Ag + go);
            cp16(smem_u32(&Bs[off]), Bg + go);
        }
        asm volatile("cp.async.commit_group;");
    };

    load_tile(0);
    if (T > 1) load_tile(1);

    const int a_r = lane & 15;
    const int a_c = lane >> 4;
    const int b_r = ((lane >> 4) << 3) + (lane & 7);
    const int b_c = (lane >> 3) & 1;

    for (int t = 0; t < T; t++) {
        asm volatile("cp.async.wait_group 1;");
        __syncthreads();
        if (t + 2 < T) load_tile(t + 2);

        const __half* Ab = hs + (t % 3) * HG_STG;
        const __half* Bb = Ab + HG_OPH;
#pragma unroll
        for (int kc = 0; kc < 4; kc++) {
            uint32_t a[4][4], b[8][2];
#pragma unroll
            for (int mi = 0; mi < 4; mi++) {
                uint32_t ad = smem_u32(&Ab[sw_off(wm + mi * 16 + a_r, kc * 2 + a_c)]);
                LDSM_X4(a[mi], ad);
            }
#pragma unroll
            for (int p = 0; p < 4; p++) {
                uint32_t br[4];
                uint32_t bd = smem_u32(&Bb[sw_off(wn + p * 16 + b_r, kc * 2 + b_c)]);
                LDSM_X4(br, bd);
                b[2 * p][0] = br[0]; b[2 * p][1] = br[1];
                b[2 * p + 1][0] = br[2]; b[2 * p + 1][1] = br[3];
            }
#pragma unroll
            for (int mi = 0; mi < 4; mi++)
#pragma unroll
                for (int ni = 0; ni < 8; ni++)
                    MMA_F16(acc[mi * 8 + ni], a[mi], b[ni]);
        }
    }

    if (Ch) {
#pragma unroll
        for (int mi = 0; mi < 4; mi++) {
            int r0 = bm * 128 + wm + mi * 16 + g;
#pragma unroll
            for (int ni = 0; ni < 8; ni++) {
                int c = bn * 128 + wn + ni * 8 + tg * 2;
                __half* p = Ch + (size_t)r0 * N + c;
                __half2 v0 = __floats2half2_rn(acc[mi * 8 + ni][0], acc[mi * 8 + ni][1]);
                __half2 v1 = __floats2half2_rn(acc[mi * 8 + ni][2], acc[mi * 8 + ni][3]);
                *(__half2*)p = v0;
                *(__half2*)(p + (size_t)8 * N) = v1;
            }
        }
        if (asp) {
            // fused alphas partials: per row, dot of C fragment with a_s/a_d over
            // this warp's 64-col slice. Deterministic: fixed ni order + fixed
            // shfl_xor(1),shfl_xor(2) combine over the 4 lanes sharing a row.
            int slice = bn * 2 + (wn >> 6);
#pragma unroll
            for (int mi = 0; mi < 4; mi++) {
                float ps0 = 0.f, ps1 = 0.f, pd0 = 0.f, pd1 = 0.f;
#pragma unroll
                for (int ni = 0; ni < 8; ni++) {
                    int cl = wn + ni * 8 + tg * 2;   // col within 128-wide tile
                    float a0 = s_as[cl], a1 = s_as[cl + 1];
                    float d0 = s_ad[cl], d1 = s_ad[cl + 1];
                    const float* ac = acc[mi * 8 + ni];
                    ps0 += ac[0] * a0 + ac[1] * a1;
                    ps1 += ac[2] * a0 + ac[3] * a1;
                    pd0 += ac[0] * d0 + ac[1] * d1;
                    pd1 += ac[2] * d0 + ac[3] * d1;
                }
#pragma unroll
                for (int o = 1; o <= 2; o <<= 1) {
                    ps0 += __shfl_xor_sync(0xffffffffu, ps0, o);
                    ps1 += __shfl_xor_sync(0xffffffffu, ps1, o);
                    pd0 += __shfl_xor_sync(0xffffffffu, pd0, o);
                    pd1 += __shfl_xor_sync(0xffffffffu, pd1, o);
                }
                if (tg == 0) {
                    int r0 = bm * 128 + wm + mi * 16 + g;
                    asp[(size_t)r0 * NSLICE + slice] = ps0;
                    asp[(size_t)(r0 + 8) * NSLICE + slice] = ps1;
                    adp[(size_t)r0 * NSLICE + slice] = pd0;
                    adp[(size_t)(r0 + 8) * NSLICE + slice] = pd1;
                }
            }
        }
    } else {
        float* Cp = Cf + (size_t)bz * NNODES * DHID;
#pragma unroll
        for (int mi = 0; mi < 4; mi++) {
            int r0 = bm * 128 + wm + mi * 16 + g;
#pragma unroll
            for (int ni = 0; ni < 8; ni++) {
                int c = bn * 128 + wn + ni * 8 + tg * 2;
                float* p = Cp + (size_t)r0 * N + c;
                *(float2*)p = make_float2(acc[mi * 8 + ni][0], acc[mi * 8 + ni][1]);
                *(float2*)(p + (size_t)8 * N) = make_float2(acc[mi * 8 + ni][2], acc[mi * 8 + ni][3]);
            }
        }
    }
}

// ---------------- alphas1 slice reduction (deterministic fixed order) ----------------
// thread per (node, head): as1 = sum of 12 slices [head*12 .. head*12+12)
__global__ void reduce_alphas1_kernel(float* __restrict__ out_s, float* __restrict__ out_d)
{
    int idx = blockIdx.x * blockDim.x + threadIdx.x;
    if (idx >= NNODES * H1N) return;
    int n = idx / H1N, hd = idx % H1N;
    const float* ps = g_asp + (size_t)n * NSLICE + hd * 12;
    const float* pd = g_adp + (size_t)n * NSLICE + hd * 12;
    float ss = 0.f, sd = 0.f;
#pragma unroll
    for (int i = 0; i < 12; i++) { ss += ps[i]; sd += pd[i]; }
    out_s[idx] = ss;
    out_d[idx] = sd;
}

// ---------------- split-K reduce + layer-2 alphas (fused) ----------------
__global__ void reduce_alphas2_kernel(const float* __restrict__ part,
                                      float* __restrict__ h2,
                                      const float* __restrict__ a_s, const float* __restrict__ a_d,
                                      float* __restrict__ out_s, float* __restrict__ out_d)
{
    int w = (blockIdx.x * blockDim.x + threadIdx.x) >> 5;
    int lane = threadIdx.x & 31;
    if (w >= NNODES) return;
    const size_t base = (size_t)w * DHID;
    const size_t pstride = (size_t)NNODES * DHID;
    float ss = 0.f, sd = 0.f;
    for (int c = lane; c < DHID; c += 32) {
        float s = part[base + c] + part[pstride + base + c] + part[2 * pstride + base + c];
        h2[base + c] = s;
        ss += s * a_s[c];
        sd += s * a_d[c];
    }
#pragma unroll
    for (int o = 16; o; o >>= 1) {
        ss += __shfl_down_sync(0xffffffffu, ss, o);
        sd += __shfl_down_sync(0xffffffffu, sd, o);
    }
    if (lane == 0) { out_s[w] = ss; out_d[w] = sd; }
}

// ---------------- per-(dst,head) segment softmax ----------------
__global__ void softmax_kernel(const int* __restrict__ src,
                               const float* __restrict__ as, const float* __restrict__ ad,
                               float* __restrict__ alpha, int H)
{
    int idx = blockIdx.x * blockDim.x + threadIdx.x;
    if (idx >= NNODES * H) return;
    int d = idx / H, hd = idx % H;
    int s0 = g_off[d], s1 = g_off[d + 1];
    if (s0 == s1) return;
    float adv = ad[idx];

    float m = -1e30f;
    for (int i = s0; i < s1; i++) {
        int e = g_eid[i];
        float x = as[src[e] * H + hd] + adv;
        x = (x > 0.f) ? x : NEG_SLOPE * x;
        m = fmaxf(m, x);
    }
    float sum = 0.f;
    for (int i = s0; i < s1; i++) {
        int e = g_eid[i];
        float x = as[src[e] * H + hd] + adv;
        x = (x > 0.f) ? x : NEG_SLOPE * x;
        float w = __expf(x - m);
        alpha[(size_t)e * H + hd] = w;
        sum += w;
    }
    float inv = 1.f / (sum + EPSV);
    for (int i = s0; i < s1; i++) {
        int e = g_eid[i];
        alpha[(size_t)e * H + hd] *= inv;
    }
}

// ---------------- layer-1 aggregation: one block per node, all heads ----------------
__global__ void __launch_bounds__(256)
aggregate1_kernel(const int* __restrict__ src, const float* __restrict__ alpha,
                  const __half* __restrict__ h, __half* __restrict__ out_h,
                  const float* __restrict__ bias)
{
    int d  = blockIdx.x;
    int t  = threadIdx.x;
    int hd = t >> 5;
    size_t rowoff = (size_t)hd * DHID + (size_t)(t & 31) * 24;
    int s0 = g_off[d], s1 = g_off[d + 1];
    const size_t rs = (size_t)H1N * DHID;

    float acc[24];
#pragma unroll
    for (int j = 0; j < 24; j++) acc[j] = 0.f;

    for (int i = s0; i < s1; i++) {
        int e = g_eid[i];
        float a = alpha[(size_t)e * H1N + hd];
        const uint4* p = (const uint4*)(h + (size_t)src[e] * rs + rowoff);
#pragma unroll
        for (int j = 0; j < 3; j++) {
            uint4 u = p[j];
            const __half2* hh = (const __half2*)&u;
#pragma unroll
            for (int k = 0; k < 4; k++) {
                float2 f = __half22float2(hh[k]);
                acc[j * 8 + k * 2]     += a * f.x;
                acc[j * 8 + k * 2 + 1] += a * f.y;
            }
        }
    }

    const float* bp = bias + rowoff;
    __half* op = out_h + (size_t)d * rs + rowoff;
#pragma unroll
    for (int j = 0; j < 3; j++) {
        uint4 u;
        __half2* hh = (__half2*)&u;
#pragma unroll
        for (int k = 0; k < 4; k++) {
            float v0 = acc[j * 8 + k * 2]     + bp[j * 8 + k * 2];
            float v1 = acc[j * 8 + k * 2 + 1] + bp[j * 8 + k * 2 + 1];
            v0 = (v0 > 0.f) ? v0 : expm1f(v0);
            v1 = (v1 > 0.f) ? v1 : expm1f(v1);
            hh[k] = __floats2half2_rn(v0, v1);
        }
        ((uint4*)op)[j] = u;
    }
}

// ---------------- layer-2 aggregation: fp32 gather, fp32 out ----------------
__global__ void __launch_bounds__(192)
aggregate2_kernel(const int* __restrict__ src, const float* __restrict__ alpha,
                  const float* __restrict__ h, float* __restrict__ out,
                  const float* __restrict__ bias)
{
    int d = blockIdx.x;
    int t = threadIdx.x;
    int s0 = g_off[d], s1 = g_off[d + 1];

    float4 acc = make_float4(0.f, 0.f, 0.f, 0.f);
    for (int i = s0; i < s1; i++) {
        int e = g_eid[i];
        float a = alpha[e];
        float4 v = *(((const float4*)(h + (size_t)src[e] * DHID)) + t);
        acc.x += a * v.x; acc.y += a * v.y; acc.z += a * v.z; acc.w += a * v.w;
    }
    float4 b = *(((const float4*)bias) + t);
    acc.x += b.x; acc.y += b.y; acc.z += b.z; acc.w += b.w;
    *(((float4*)(out + (size_t)d * DHID)) + t) = acc;
}

// ---------------- launch ----------------
extern "C" void kernel_launch(void* const* d_in, const int* in_sizes, int n_in,
                              void* d_out, int out_size)
{
    const float* x    = (const float*)d_in[0];
    const float* W1   = (const float*)d_in[1];
    const float* a_s1 = (const float*)d_in[2];
    const float* a_d1 = (const float*)d_in[3];
    const float* b1   = (const float*)d_in[4];
    const float* W2   = (const float*)d_in[5];
    const float* a_s2 = (const float*)d_in[6];
    const float* a_d2 = (const float*)d_in[7];
    const float* b2   = (const float*)d_in[8];
    const int* edges  = (const int*)d_in[9];
    const int* src = edges;
    const int* dst = edges + NEDGES;
    float* out = (float*)d_out;

    float *part, *h2, *as1, *ad1, *as2, *ad2, *al1, *al2, *aspp, *adpp;
    __half *h1h, *xh, *o1h, *w1th, *w2th;
    cudaGetSymbolAddress((void**)&h1h,  g_h1h);
    cudaGetSymbolAddress((void**)&part, g_part);
    cudaGetSymbolAddress((void**)&h2,   g_h2);
    cudaGetSymbolAddress((void**)&xh,   g_xh);
    cudaGetSymbolAddress((void**)&o1h,  g_o1h);
    cudaGetSymbolAddress((void**)&w1th, g_w1th);
    cudaGetSymbolAddress((void**)&w2th, g_w2th);
    cudaGetSymbolAddress((void**)&aspp, g_asp);
    cudaGetSymbolAddress((void**)&adpp, g_adp);
    cudaGetSymbolAddress((void**)&as1,  g_as1);
    cudaGetSymbolAddress((void**)&ad1,  g_ad1);
    cudaGetSymbolAddress((void**)&as2,  g_as2);
    cudaGetSymbolAddress((void**)&ad2,  g_ad2);
    cudaGetSymbolAddress((void**)&al1,  g_alpha1);
    cudaGetSymbolAddress((void**)&al2,  g_alpha2);

    cudaFuncSetAttribute(hgemm, cudaFuncAttributeMaxDynamicSharedMemorySize, HG_SMEM);

    // Streams/events created once on the (uncaptured) first call.
    static cudaStream_t s2 = nullptr, s3 = nullptr;
    static cudaEvent_t evFork = nullptr, evJoin2 = nullptr, evJoin3 = nullptr;
    if (!s2) {
        cudaStreamCreateWithFlags(&s2, cudaStreamNonBlocking);
        cudaStreamCreateWithFlags(&s3, cudaStreamNonBlocking);
        cudaEventCreateWithFlags(&evFork,  cudaEventDisableTiming);
        cudaEventCreateWithFlags(&evJoin2, cudaEventDisableTiming);
        cudaEventCreateWithFlags(&evJoin3, cudaEventDisableTiming);
    }

    dim3 tblk(32, 8);

    // ---- fork ----
    cudaEventRecord(evFork, 0);
    cudaStreamWaitEvent(s2, evFork, 0);
    cudaStreamWaitEvent(s3, evFork, 0);

    // s2: CSR chain + W2 transpose
    zero_counts_kernel<<<(NNODES + 255) / 256, 256, 0, s2>>>();
    count_kernel<<<(NEDGES + 255) / 256, 256, 0, s2>>>(dst);
    scan_kernel<<<1, 1024, 0, s2>>>();
    scatter_kernel<<<(NEDGES + 255) / 256, 256, 0, s2>>>(dst);
    sort_eid_kernel<<<(NNODES + 255) / 256, 256, 0, s2>>>();
    {
        dim3 gt(DHID / 32, (H1N * DHID) / 32);
        transpose_h_kernel<<<gt, tblk, 0, s2>>>(W2, w2th, H1N * DHID, DHID);
    }
    cudaEventRecord(evJoin2, s2);

    // s3: W1 transpose
    {
        dim3 gt((H1N * DHID) / 32, DIN / 32);
        transpose_h_kernel<<<gt, tblk, 0, s3>>>(W1, w1th, DIN, H1N * DHID);
    }
    cudaEventRecord(evJoin3, s3);

    // ---- main chain ----
    f2h_kernel<<<(NNODES * DIN / 4 + 255) / 256, 256>>>(x, xh, NNODES * DIN / 4);
    cudaStreamWaitEvent(0, evJoin3, 0);
    {
        dim3 grid((H1N * DHID) / 128, NNODES / 128, 1);   // (48, 64)
        hgemm<<<grid, 128, HG_SMEM>>>(xh, w1th, nullptr, h1h, a_s1, a_d1, aspp, adpp,
                                      DIN, DIN, H1N * DHID);
    }
    reduce_alphas1_kernel<<<(NNODES * H1N + 255) / 256, 256>>>(as1, ad1);

    cudaStreamWaitEvent(0, evJoin2, 0);

    softmax_kernel<<<(NNODES * H1N + 255) / 256, 256>>>(src, as1, ad1, al1, H1N);
    aggregate1_kernel<<<NNODES, 256>>>(src, al1, h1h, o1h, b1);
    {
        dim3 grid((H2N * DHID) / 128, NNODES / 128, SPLITK);   // (6, 64, 3)
        hgemm<<<grid, 128, HG_SMEM>>>(o1h, w2th, part, nullptr, nullptr, nullptr,
                                      nullptr, nullptr, H1N * DHID, K2CHUNK, H2N * DHID);
    }
    reduce_alphas2_kernel<<<(NNODES * 32 + 255) / 256, 256>>>(part, h2, a_s2, a_d2, as2, ad2);
    softmax_kernel<<<(NNODES + 255) / 256, 256>>>(src, as2, ad2, al2, H2N);
    aggregate2_kernel<<<NNODES, DHID / 4>>>(src, al2, h2, out, b2);
}

// round 17
// speedup vs baseline: 1.0824x; 1.0097x over previous
#include <cuda_runtime.h>
#include <cuda_fp16.h>
#include <math.h>
#include <cstdint>

// ---------------- problem constants ----------------
#define NNODES 8192
#define NEDGES 65536
#define DIN    768
#define DHID   768
#define H1N    8
#define H2N    1
#define NEG_SLOPE 0.2f
#define EPSV 1e-16f
#define SPLITK 3
#define K2CHUNK ((H1N * DHID) / SPLITK)     // 2048
#define NSLICE 96                            // 48 bn-tiles x 2 wn-halves

// ---------------- scratch (device globals; no allocs allowed) ----------------
__device__ __half g_h1h[(size_t)NNODES * (H1N * DHID)];    // x @ W1 fp16 [8192, 6144]
__device__ __half g_parth[(size_t)SPLITK * NNODES * DHID]; // GEMM2 split-K partials fp16
__device__ __half g_h2h[(size_t)NNODES * DHID];            // o1 @ W2 summed fp16
__device__ __half g_xh [(size_t)NNODES * DIN];             // x fp16
__device__ __half g_o1h[(size_t)NNODES * (H1N * DHID)];    // elu(agg1+b1) fp16 (GEMM2 A)
__device__ __half g_w1th[(size_t)(H1N * DHID) * DIN];      // W1^T fp16 [6144, 768]
__device__ __half g_w2th[(size_t)DHID * (H1N * DHID)];     // W2^T fp16 [768, 6144]
__device__ float g_asp[(size_t)NNODES * NSLICE];           // alphas1 slice partials (a_src)
__device__ float g_adp[(size_t)NNODES * NSLICE];           // alphas1 slice partials (a_dst)
__device__ float g_as1[NNODES * H1N];
__device__ float g_ad1[NNODES * H1N];
__device__ float g_as2[NNODES];
__device__ float g_ad2[NNODES];
__device__ float g_alpha1[(size_t)NEDGES * H1N];
__device__ float g_alpha2[(size_t)NEDGES];
__device__ int   g_deg[NNODES];
__device__ int   g_cur[NNODES];
__device__ int   g_off[NNODES + 1];
__device__ int   g_eid[NEDGES];

// ---------------- helpers ----------------
__device__ __forceinline__ void cp16(unsigned dst, const void* src) {
    asm volatile("cp.async.cg.shared.global [%0], [%1], 16;" :: "r"(dst), "l"(src));
}
__device__ __forceinline__ uint32_t smem_u32(const void* p) {
    return (uint32_t)__cvta_generic_to_shared(p);
}

#define MMA_F16(d, a, b)                                                               \
    asm volatile(                                                                      \
        "mma.sync.aligned.m16n8k16.row.col.f32.f16.f16.f32 "                           \
        "{%0,%1,%2,%3},{%4,%5,%6,%7},{%8,%9},{%0,%1,%2,%3};"                           \
        : "+f"((d)[0]), "+f"((d)[1]), "+f"((d)[2]), "+f"((d)[3])                       \
        : "r"((a)[0]), "r"((a)[1]), "r"((a)[2]), "r"((a)[3]), "r"((b)[0]), "r"((b)[1]))

#define LDSM_X4(r, addr)                                                               \
    asm volatile("ldmatrix.sync.aligned.m8n8.x4.shared.b16 {%0,%1,%2,%3}, [%4];"       \
        : "=r"((r)[0]), "=r"((r)[1]), "=r"((r)[2]), "=r"((r)[3]) : "r"(addr))

// ---------------- fp32 -> fp16 convert ----------------
__global__ void f2h_kernel(const float* __restrict__ in, __half* __restrict__ out, int n4) {
    int i = blockIdx.x * blockDim.x + threadIdx.x;
    if (i < n4) {
        float4 v = ((const float4*)in)[i];
        __half2 h0 = __floats2half2_rn(v.x, v.y);
        __half2 h1 = __floats2half2_rn(v.z, v.w);
        uint2 u;
        u.x = *(uint32_t*)&h0; u.y = *(uint32_t*)&h1;
        ((uint2*)out)[i] = u;
    }
}

// ---------------- transpose + fp16 convert: in [R,C] fp32 -> out [C,R] fp16 ----------------
__global__ void transpose_h_kernel(const float* __restrict__ in, __half* __restrict__ out,
                                   int R, int C)
{
    __shared__ float t[32][33];
    int bx = blockIdx.x * 32, by = blockIdx.y * 32;
#pragma unroll
    for (int i = 0; i < 4; i++)
        t[threadIdx.y + 8 * i][threadIdx.x] =
            in[(size_t)(by + threadIdx.y + 8 * i) * C + bx + threadIdx.x];
    __syncthreads();
#pragma unroll
    for (int i = 0; i < 4; i++)
        out[(size_t)(bx + threadIdx.y + 8 * i) * R + by + threadIdx.x] =
            __float2half_rn(t[threadIdx.x][threadIdx.y + 8 * i]);
}

// ---------------- CSR build ----------------
__global__ void zero_counts_kernel() {
    int i = blockIdx.x * blockDim.x + threadIdx.x;
    if (i < NNODES) { g_deg[i] = 0; g_cur[i] = 0; }
}
__global__ void count_kernel(const int* __restrict__ dst) {
    int e = blockIdx.x * blockDim.x + threadIdx.x;
    if (e < NEDGES) atomicAdd(&g_deg[dst[e]], 1);
}
__global__ void scan_kernel() {
    __shared__ int s[1024];
    int t = threadIdx.x;
    int base = t * 8;
    int local[8];
    int run = 0;
#pragma unroll
    for (int i = 0; i < 8; i++) { local[i] = run; run += g_deg[base + i]; }
    s[t] = run;
    __syncthreads();
    for (int o = 1; o < 1024; o <<= 1) {
        int v = (t >= o) ? s[t - o] : 0;
        __syncthreads();
        s[t] += v;
        __syncthreads();
    }
    int prev = (t == 0) ? 0 : s[t - 1];
#pragma unroll
    for (int i = 0; i < 8; i++) g_off[base + i] = prev + local[i];
    if (t == 1023) g_off[NNODES] = s[1023];
}
__global__ void scatter_kernel(const int* __restrict__ dst) {
    int e = blockIdx.x * blockDim.x + threadIdx.x;
    if (e < NEDGES) {
        int d = dst[e];
        int p = atomicAdd(&g_cur[d], 1);
        g_eid[g_off[d] + p] = e;
    }
}
// Deterministic segment ordering (freezes all downstream fp32 sum orders).
__global__ void sort_eid_kernel() {
    int d = blockIdx.x * blockDim.x + threadIdx.x;
    if (d >= NNODES) return;
    int s0 = g_off[d], s1 = g_off[d + 1];
    for (int i = s0 + 1; i < s1; i++) {
        int v = g_eid[i];
        int j = i - 1;
        while (j >= s0 && g_eid[j] > v) { g_eid[j + 1] = g_eid[j]; j--; }
        g_eid[j + 1] = v;
    }
}

// ---------------- fp16 tensor-core GEMM (+ optional fused alphas partials) ----------------
// Block 128x128, 4 warps (2x2), warp tile 64x64.  K-tile 64, 3-stage cp.async, ldmatrix.
// XOR-swizzled smem rows of exactly 128B.  One barrier per K-iteration.
// Output: fp16 to Ch + bz * NNODES * N (bz = split-K partial index; 0 for GEMM1).
// When asp != nullptr (GEMM1): fused per-row dots of C with a_s/a_d over this warp's
// 64-col slice -> asp/adp[row * NSLICE + bn*2 + wn/64].
#define KT 64
#define HG_OPH  (128 * KT)
#define HG_STG  (2 * HG_OPH)
#define HG_SMEM (3 * HG_STG * 2)           // 98304 bytes

__device__ __forceinline__ int sw_off(int r, int c) {
    return r * KT + ((c ^ (r & 7)) << 3);
}

__global__ void __launch_bounds__(128, 2)
hgemm(const __half* __restrict__ A, const __half* __restrict__ Bt,
      __half* __restrict__ Ch,
      const float* __restrict__ a_s, const float* __restrict__ a_d,
      float* __restrict__ asp, float* __restrict__ adp,
      int lda, int kLen, int N)
{
    extern __shared__ __half hs[];
    __shared__ float s_as[128], s_ad[128];

    const int tid = threadIdx.x, wid = tid >> 5, lane = tid & 31;
    const int bn = blockIdx.x, bm = blockIdx.y, bz = blockIdx.z;
    const int k0 = bz * kLen;
    const int wm = (wid & 1) * 64;
    const int wn = (wid >> 1) * 64;
    const int g = lane >> 2, tg = lane & 3;

    if (asp && tid < 128) {
        s_as[tid] = a_s[bn * 128 + tid];
        s_ad[tid] = a_d[bn * 128 + tid];
    }

    const __half* Ag = A + (size_t)(bm * 128) * lda + k0;
    const __half* Bg = Bt + (size_t)(bn * 128) * lda + k0;

    float acc[32][4] = {};
    const int T = kLen / KT;

    auto load_tile = [&](int t) {
        int st = t % 3;
        __half* As = hs + st * HG_STG;
        __half* Bs = As + HG_OPH;
        int kk = t * KT;
#pragma unroll
        for (int i = 0; i < 8; i++) {
            int ci = tid + i * 128;
            int r = ci >> 3, c = ci & 7;
            int off = sw_off(r, c);
            const size_t go = (size_t)r * lda + kk + c * 8;
            cp16(smem_u32(&As[off]), Ag + go);
            cp16(smem_u32(&Bs[off]), Bg + go);
        }
        asm volatile("cp.async.commit_group;");
    };

    load_tile(0);
    if (T > 1) load_tile(1);

    const int a_r = lane & 15;
    const int a_c = lane >> 4;
    const int b_r = ((lane >> 4) << 3) + (lane & 7);
    const int b_c = (lane >> 3) & 1;

    for (int t = 0; t < T; t++) {
        asm volatile("cp.async.wait_group 1;");
        __syncthreads();
        if (t + 2 < T) load_tile(t + 2);

        const __half* Ab = hs + (t % 3) * HG_STG;
        const __half* Bb = Ab + HG_OPH;
#pragma unroll
        for (int kc = 0; kc < 4; kc++) {
            uint32_t a[4][4], b[8][2];
#pragma unroll
            for (int mi = 0; mi < 4; mi++) {
                uint32_t ad = smem_u32(&Ab[sw_off(wm + mi * 16 + a_r, kc * 2 + a_c)]);
                LDSM_X4(a[mi], ad);
            }
#pragma unroll
            for (int p = 0; p < 4; p++) {
                uint32_t br[4];
                uint32_t bd = smem_u32(&Bb[sw_off(wn + p * 16 + b_r, kc * 2 + b_c)]);
                LDSM_X4(br, bd);
                b[2 * p][0] = br[0]; b[2 * p][1] = br[1];
                b[2 * p + 1][0] = br[2]; b[2 * p + 1][1] = br[3];
            }
#pragma unroll
            for (int mi = 0; mi < 4; mi++)
#pragma unroll
                for (int ni = 0; ni < 8; ni++)
                    MMA_F16(acc[mi * 8 + ni], a[mi], b[ni]);
        }
    }

    __half* Cp = Ch + (size_t)bz * NNODES * N;
#pragma unroll
    for (int mi = 0; mi < 4; mi++) {
        int r0 = bm * 128 + wm + mi * 16 + g;
#pragma unroll
        for (int ni = 0; ni < 8; ni++) {
            int c = bn * 128 + wn + ni * 8 + tg * 2;
            __half* p = Cp + (size_t)r0 * N + c;
            __half2 v0 = __floats2half2_rn(acc[mi * 8 + ni][0], acc[mi * 8 + ni][1]);
            __half2 v1 = __floats2half2_rn(acc[mi * 8 + ni][2], acc[mi * 8 + ni][3]);
            *(__half2*)p = v0;
            *(__half2*)(p + (size_t)8 * N) = v1;
        }
    }
    if (asp) {
        int slice = bn * 2 + (wn >> 6);
#pragma unroll
        for (int mi = 0; mi < 4; mi++) {
            float ps0 = 0.f, ps1 = 0.f, pd0 = 0.f, pd1 = 0.f;
#pragma unroll
            for (int ni = 0; ni < 8; ni++) {
                int cl = wn + ni * 8 + tg * 2;
                float a0 = s_as[cl], a1 = s_as[cl + 1];
                float d0 = s_ad[cl], d1 = s_ad[cl + 1];
                const float* ac = acc[mi * 8 + ni];
                ps0 += ac[0] * a0 + ac[1] * a1;
                ps1 += ac[2] * a0 + ac[3] * a1;
                pd0 += ac[0] * d0 + ac[1] * d1;
                pd1 += ac[2] * d0 + ac[3] * d1;
            }
#pragma unroll
            for (int o = 1; o <= 2; o <<= 1) {
                ps0 += __shfl_xor_sync(0xffffffffu, ps0, o);
                ps1 += __shfl_xor_sync(0xffffffffu, ps1, o);
                pd0 += __shfl_xor_sync(0xffffffffu, pd0, o);
                pd1 += __shfl_xor_sync(0xffffffffu, pd1, o);
            }
            if (tg == 0) {
                int r0 = bm * 128 + wm + mi * 16 + g;
                asp[(size_t)r0 * NSLICE + slice] = ps0;
                asp[(size_t)(r0 + 8) * NSLICE + slice] = ps1;
                adp[(size_t)r0 * NSLICE + slice] = pd0;
                adp[(size_t)(r0 + 8) * NSLICE + slice] = pd1;
            }
        }
    }
}

// ---------------- alphas1 slice reduction (deterministic fixed order) ----------------
__global__ void reduce_alphas1_kernel(float* __restrict__ out_s, float* __restrict__ out_d)
{
    int idx = blockIdx.x * blockDim.x + threadIdx.x;
    if (idx >= NNODES * H1N) return;
    int n = idx / H1N, hd = idx % H1N;
    const float* ps = g_asp + (size_t)n * NSLICE + hd * 12;
    const float* pd = g_adp + (size_t)n * NSLICE + hd * 12;
    float ss = 0.f, sd = 0.f;
#pragma unroll
    for (int i = 0; i < 12; i++) { ss += ps[i]; sd += pd[i]; }
    out_s[idx] = ss;
    out_d[idx] = sd;
}

// ---------------- split-K reduce (fp16 partials) + layer-2 alphas ----------------
// warp per node: lane handles 24 contiguous cols; h2h = fp16(p0+p1+p2); dots in fp32.
__global__ void reduce_alphas2_kernel(const __half* __restrict__ parth,
                                      __half* __restrict__ h2h,
                                      const float* __restrict__ a_s, const float* __restrict__ a_d,
                                      float* __restrict__ out_s, float* __restrict__ out_d)
{
    int w = (blockIdx.x * blockDim.x + threadIdx.x) >> 5;
    int lane = threadIdx.x & 31;
    if (w >= NNODES) return;
    const size_t base = (size_t)w * DHID + lane * 24;
    const size_t pstride = (size_t)NNODES * DHID;

    float ss = 0.f, sd = 0.f;
#pragma unroll
    for (int j = 0; j < 3; j++) {
        uint4 u0 = *(const uint4*)(parth + base + j * 8);
        uint4 u1 = *(const uint4*)(parth + pstride + base + j * 8);
        uint4 u2 = *(const uint4*)(parth + 2 * pstride + base + j * 8);
        const __half2* h0 = (const __half2*)&u0;
        const __half2* h1 = (const __half2*)&u1;
        const __half2* h2p = (const __half2*)&u2;
        uint4 uo;
        __half2* ho = (__half2*)&uo;
#pragma unroll
        for (int k = 0; k < 4; k++) {
            float2 f0 = __half22float2(h0[k]);
            float2 f1 = __half22float2(h1[k]);
            float2 f2 = __half22float2(h2p[k]);
            float v0 = f0.x + f1.x + f2.x;
            float v1 = f0.y + f1.y + f2.y;
            int col = lane * 24 + j * 8 + k * 2;
            ss += v0 * a_s[col] + v1 * a_s[col + 1];
            sd += v0 * a_d[col] + v1 * a_d[col + 1];
            ho[k] = __floats2half2_rn(v0, v1);
        }
        *(uint4*)(h2h + base + j * 8) = uo;
    }
#pragma unroll
    for (int o = 16; o; o >>= 1) {
        ss += __shfl_down_sync(0xffffffffu, ss, o);
        sd += __shfl_down_sync(0xffffffffu, sd, o);
    }
    if (lane == 0) { out_s[w] = ss; out_d[w] = sd; }
}

// ---------------- per-(dst,head) segment softmax ----------------
__global__ void softmax_kernel(const int* __restrict__ src,
                               const float* __restrict__ as, const float* __restrict__ ad,
                               float* __restrict__ alpha, int H)
{
    int idx = blockIdx.x * blockDim.x + threadIdx.x;
    if (idx >= NNODES * H) return;
    int d = idx / H, hd = idx % H;
    int s0 = g_off[d], s1 = g_off[d + 1];
    if (s0 == s1) return;
    float adv = ad[idx];

    float m = -1e30f;
    for (int i = s0; i < s1; i++) {
        int e = g_eid[i];
        float x = as[src[e] * H + hd] + adv;
        x = (x > 0.f) ? x : NEG_SLOPE * x;
        m = fmaxf(m, x);
    }
    float sum = 0.f;
    for (int i = s0; i < s1; i++) {
        int e = g_eid[i];
        float x = as[src[e] * H + hd] + adv;
        x = (x > 0.f) ? x : NEG_SLOPE * x;
        float w = __expf(x - m);
        alpha[(size_t)e * H + hd] = w;
        sum += w;
    }
    float inv = 1.f / (sum + EPSV);
    for (int i = s0; i < s1; i++) {
        int e = g_eid[i];
        alpha[(size_t)e * H + hd] *= inv;
    }
}

// ---------------- layer-1 aggregation: one block per node, all heads ----------------
__global__ void __launch_bounds__(256)
aggregate1_kernel(const int* __restrict__ src, const float* __restrict__ alpha,
                  const __half* __restrict__ h, __half* __restrict__ out_h,
                  const float* __restrict__ bias)
{
    int d  = blockIdx.x;
    int t  = threadIdx.x;
    int hd = t >> 5;
    size_t rowoff = (size_t)hd * DHID + (size_t)(t & 31) * 24;
    int s0 = g_off[d], s1 = g_off[d + 1];
    const size_t rs = (size_t)H1N * DHID;

    float acc[24];
#pragma unroll
    for (int j = 0; j < 24; j++) acc[j] = 0.f;

    for (int i = s0; i < s1; i++) {
        int e = g_eid[i];
        float a = alpha[(size_t)e * H1N + hd];
        const uint4* p = (const uint4*)(h + (size_t)src[e] * rs + rowoff);
#pragma unroll
        for (int j = 0; j < 3; j++) {
            uint4 u = p[j];
            const __half2* hh = (const __half2*)&u;
#pragma unroll
            for (int k = 0; k < 4; k++) {
                float2 f = __half22float2(hh[k]);
                acc[j * 8 + k * 2]     += a * f.x;
                acc[j * 8 + k * 2 + 1] += a * f.y;
            }
        }
    }

    const float* bp = bias + rowoff;
    __half* op = out_h + (size_t)d * rs + rowoff;
#pragma unroll
    for (int j = 0; j < 3; j++) {
        uint4 u;
        __half2* hh = (__half2*)&u;
#pragma unroll
        for (int k = 0; k < 4; k++) {
            float v0 = acc[j * 8 + k * 2]     + bp[j * 8 + k * 2];
            float v1 = acc[j * 8 + k * 2 + 1] + bp[j * 8 + k * 2 + 1];
            v0 = (v0 > 0.f) ? v0 : expm1f(v0);
            v1 = (v1 > 0.f) ? v1 : expm1f(v1);
            hh[k] = __floats2half2_rn(v0, v1);
        }
        ((uint4*)op)[j] = u;
    }
}

// ---------------- layer-2 aggregation: fp16 gather, fp32 out ----------------
// 192 threads: thread t handles cols [4t, 4t+4) (uint2 of 4 halves).
__global__ void __launch_bounds__(192)
aggregate2_kernel(const int* __restrict__ src, const float* __restrict__ alpha,
                  const __half* __restrict__ h, float* __restrict__ out,
                  const float* __restrict__ bias)
{
    int d = blockIdx.x;
    int t = threadIdx.x;
    int s0 = g_off[d], s1 = g_off[d + 1];

    float4 acc = make_float4(0.f, 0.f, 0.f, 0.f);
    for (int i = s0; i < s1; i++) {
        int e = g_eid[i];
        float a = alpha[e];
        uint2 u = *(((const uint2*)(h + (size_t)src[e] * DHID)) + t);
        float2 f0 = __half22float2(*(__half2*)&u.x);
        float2 f1 = __half22float2(*(__half2*)&u.y);
        acc.x += a * f0.x; acc.y += a * f0.y; acc.z += a * f1.x; acc.w += a * f1.y;
    }
    float4 b = *(((const float4*)bias) + t);
    acc.x += b.x; acc.y += b.y; acc.z += b.z; acc.w += b.w;
    *(((float4*)(out + (size_t)d * DHID)) + t) = acc;
}

// ---------------- launch ----------------
extern "C" void kernel_launch(void* const* d_in, const int* in_sizes, int n_in,
                              void* d_out, int out_size)
{
    const float* x    = (const float*)d_in[0];
    const float* W1   = (const float*)d_in[1];
    const float* a_s1 = (const float*)d_in[2];
    const float* a_d1 = (const float*)d_in[3];
    const float* b1   = (const float*)d_in[4];
    const float* W2   = (const float*)d_in[5];
    const float* a_s2 = (const float*)d_in[6];
    const float* a_d2 = (const float*)d_in[7];
    const float* b2   = (const float*)d_in[8];
    const int* edges  = (const int*)d_in[9];
    const int* src = edges;
    const int* dst = edges + NEDGES;
    float* out = (float*)d_out;

    float *as1, *ad1, *as2, *ad2, *al1, *al2, *aspp, *adpp;
    __half *h1h, *parth, *h2h, *xh, *o1h, *w1th, *w2th;
    cudaGetSymbolAddress((void**)&h1h,   g_h1h);
    cudaGetSymbolAddress((void**)&parth, g_parth);
    cudaGetSymbolAddress((void**)&h2h,   g_h2h);
    cudaGetSymbolAddress((void**)&xh,    g_xh);
    cudaGetSymbolAddress((void**)&o1h,   g_o1h);
    cudaGetSymbolAddress((void**)&w1th,  g_w1th);
    cudaGetSymbolAddress((void**)&w2th,  g_w2th);
    cudaGetSymbolAddress((void**)&aspp,  g_asp);
    cudaGetSymbolAddress((void**)&adpp,  g_adp);
    cudaGetSymbolAddress((void**)&as1,   g_as1);
    cudaGetSymbolAddress((void**)&ad1,   g_ad1);
    cudaGetSymbolAddress((void**)&as2,   g_as2);
    cudaGetSymbolAddress((void**)&ad2,   g_ad2);
    cudaGetSymbolAddress((void**)&al1,   g_alpha1);
    cudaGetSymbolAddress((void**)&al2,   g_alpha2);

    cudaFuncSetAttribute(hgemm, cudaFuncAttributeMaxDynamicSharedMemorySize, HG_SMEM);

    // Streams/events created once on the (uncaptured) first call.
    static cudaStream_t s2 = nullptr, s3 = nullptr;
    static cudaEvent_t evFork = nullptr, evJoin2 = nullptr, evJoin3 = nullptr;
    if (!s2) {
        cudaStreamCreateWithFlags(&s2, cudaStreamNonBlocking);
        cudaStreamCreateWithFlags(&s3, cudaStreamNonBlocking);
        cudaEventCreateWithFlags(&evFork,  cudaEventDisableTiming);
        cudaEventCreateWithFlags(&evJoin2, cudaEventDisableTiming);
        cudaEventCreateWithFlags(&evJoin3, cudaEventDisableTiming);
    }

    dim3 tblk(32, 8);

    // ---- fork ----
    cudaEventRecord(evFork, 0);
    cudaStreamWaitEvent(s2, evFork, 0);
    cudaStreamWaitEvent(s3, evFork, 0);

    // s2: CSR chain + W2 transpose
    zero_counts_kernel<<<(NNODES + 255) / 256, 256, 0, s2>>>();
    count_kernel<<<(NEDGES + 255) / 256, 256, 0, s2>>>(dst);
    scan_kernel<<<1, 1024, 0, s2>>>();
    scatter_kernel<<<(NEDGES + 255) / 256, 256, 0, s2>>>(dst);
    sort_eid_kernel<<<(NNODES + 255) / 256, 256, 0, s2>>>();
    {
        dim3 gt(DHID / 32, (H1N * DHID) / 32);
        transpose_h_kernel<<<gt, tblk, 0, s2>>>(W2, w2th, H1N * DHID, DHID);
    }
    cudaEventRecord(evJoin2, s2);

    // s3: W1 transpose
    {
        dim3 gt((H1N * DHID) / 32, DIN / 32);
        transpose_h_kernel<<<gt, tblk, 0, s3>>>(W1, w1th, DIN, H1N * DHID);
    }
    cudaEventRecord(evJoin3, s3);

    // ---- main chain ----
    f2h_kernel<<<(NNODES * DIN / 4 + 255) / 256, 256>>>(x, xh, NNODES * DIN / 4);
    cudaStreamWaitEvent(0, evJoin3, 0);
    {
        dim3 grid((H1N * DHID) / 128, NNODES / 128, 1);   // (48, 64)
        hgemm<<<grid, 128, HG_SMEM>>>(xh, w1th, h1h, a_s1, a_d1, aspp, adpp,
                                      DIN, DIN, H1N * DHID);
    }
    reduce_alphas1_kernel<<<(NNODES * H1N + 255) / 256, 256>>>(as1, ad1);

    cudaStreamWaitEvent(0, evJoin2, 0);

    softmax_kernel<<<(NNODES * H1N + 255) / 256, 256>>>(src, as1, ad1, al1, H1N);
    aggregate1_kernel<<<NNODES, 256>>>(src, al1, h1h, o1h, b1);
    {
        dim3 grid((H2N * DHID) / 128, NNODES / 128, SPLITK);   // (6, 64, 3)
        hgemm<<<grid, 128, HG_SMEM>>>(o1h, w2th, parth, nullptr, nullptr,
                                      nullptr, nullptr, H1N * DHID, K2CHUNK, H2N * DHID);
    }
    reduce_alphas2_kernel<<<(NNODES * 32 + 255) / 256, 256>>>(parth, h2h, a_s2, a_d2, as2, ad2);
    softmax_kernel<<<(NNODES + 255) / 256, 256>>>(src, as2, ad2, al2, H2N);
    aggregate2_kernel<<<NNODES, DHID / 4>>>(src, al2, h2h, out, b2);
}